// round 7
// baseline (speedup 1.0000x reference)
#include <cuda_runtime.h>
#include <math.h>
#include <stdint.h>

// Problem dims
constexpr int BATCH = 2;
constexpr int SEQ   = 1024;
constexpr int DM    = 1024;
constexpr int DIN   = 2048;
constexpr int NST   = 16;
constexpr int FH    = 2752;
constexpr int ROWS  = BATCH * SEQ;  // 2048

// Scratch
__device__ float g_h [ROWS * DM];
__device__ float g_a [ROWS * DIN];
__device__ float g_b [ROWS * DIN];
__device__ float g_y [ROWS * DIN];
__device__ float g_x2[ROWS * DM];
__device__ float g_bc[ROWS * 2 * NST];
__device__ float g_g [ROWS * FH];

constexpr int S = 20;            // smem row stride (floats), conflict-free
constexpr int STAGES = 4;
constexpr float CBIAS = 1.00048828125f;   // 1 + 2^-11 tf32-truncation compensation

__device__ __forceinline__ uint32_t s2u(const void* p) {
    uint32_t a;
    asm("{ .reg .u64 t; cvta.to.shared.u64 t, %1; cvt.u32.u64 %0, t; }" : "=r"(a) : "l"(p));
    return a;
}
__device__ __forceinline__ void cpa16(uint32_t dst, const float* src, int szbytes) {
    asm volatile("cp.async.cg.shared.global [%0], [%1], 16, %2;"
                 :: "r"(dst), "l"(src), "r"(szbytes));
}
#define CP_COMMIT() asm volatile("cp.async.commit_group;" ::: "memory")
#define CP_WAIT2()  asm volatile("cp.async.wait_group 2;" ::: "memory")

__device__ __forceinline__ void mma_tf32(float c[4],
                                         uint32_t a0, uint32_t a1, uint32_t a2, uint32_t a3,
                                         uint32_t b0, uint32_t b1) {
    asm volatile(
        "mma.sync.aligned.m16n8k8.row.col.f32.tf32.tf32.f32 "
        "{%0,%1,%2,%3}, {%4,%5,%6,%7}, {%8,%9}, {%0,%1,%2,%3};"
        : "+f"(c[0]), "+f"(c[1]), "+f"(c[2]), "+f"(c[3])
        : "r"(a0), "r"(a1), "r"(a2), "r"(a3), "r"(b0), "r"(b1));
}

enum { EP_NONE = 0, EP_ADD, EP_GATEMUL, EP_SOFTPLUS, EP_SILUMUL };

__device__ __forceinline__ float sigm(float x) { return 1.0f / (1.0f + expf(-x)); }
__device__ __forceinline__ float sftp(float x) { return (x > 20.0f) ? x : log1pf(expf(x)); }

// ---------------------------------------------------------------------------
// tf32 GEMM, warp tile 64x64 (MT=4, NT=8), BM=128, BN template (128 or 256).
// NTH = 2*BN/... : BN=256 -> 256 thr (8 warps 2x4); BN=128 -> 128 thr (4 warps 2x2).
// 4-stage cp.async pipeline.  bytes/MMA = 128 (crossbar-limited ~59% tensor).
// Optional folded side-block (last blockIdx.x): C2 = A @ W2^T, N2=32.
// ---------------------------------------------------------------------------
template<int EP, int BN, int NTH>
__global__ void __launch_bounds__(NTH, (NTH == 128) ? 2 : 1) gemm_ca(
    const float* __restrict__ A, const float* __restrict__ W,
    const float* __restrict__ R, const float* __restrict__ bias,
    float* __restrict__ C, int M, int N, int K,
    const float* __restrict__ W2, float* __restrict__ C2)
{
    constexpr int MT = 4, NT = 8;
    constexpr int WN_CNT = BN / 64;          // warps along N
    constexpr int AJ = 512 / NTH;            // A float4 loads per thread
    constexpr int BJ = BN * 4 / NTH;         // B float4 loads per thread (=4)
    constexpr int RSTEP = NTH / 4;           // rows covered per load step
    constexpr int ASTG = 128 * S;            // A floats per stage
    constexpr int BSTG = BN * S;             // B floats per stage

    extern __shared__ float sm[];
    float* As = sm;
    float* Bs = sm + STAGES * ASTG;
    const uint32_t sbA = s2u(As), sbB = s2u(Bs);

    const int tid  = threadIdx.x;
    const int wid  = tid >> 5, lane = tid & 31;
    const int wm   = wid / WN_CNT, wn = wid % WN_CNT;
    const int bm   = blockIdx.y << 7;
    const int bx   = blockIdx.x;
    const bool isbc = (W2 != nullptr) && (bx == (int)gridDim.x - 1);
    const int bn   = isbc ? 0 : bx * BN;
    const int Nw   = isbc ? 32 : N;
    const float* Wk = isbc ? W2 : W;
    const int lr   = lane >> 2, lc = lane & 3;

    float acc[MT][NT][4];
    #pragma unroll
    for (int i = 0; i < MT; i++)
        #pragma unroll
        for (int j = 0; j < NT; j++)
            #pragma unroll
            for (int q = 0; q < 4; q++) acc[i][j][q] = 0.0f;

    const int row0 = tid >> 2;
    const int kcol = (tid & 3) << 2;
    const int NS   = K >> 4;

    const float* asrc[AJ];
    uint32_t     adst[AJ];
    #pragma unroll
    for (int j = 0; j < AJ; j++) {
        const int r = row0 + RSTEP * j;
        asrc[j] = A + (size_t)(bm + r) * K + kcol;
        adst[j] = sbA + (uint32_t)((r * S + kcol) << 2);
    }
    const float* bsrc[BJ];
    uint32_t     bdst[BJ];
    int          bval[BJ];
    #pragma unroll
    for (int j = 0; j < BJ; j++) {
        const int r = row0 + RSTEP * j;
        bval[j] = (bn + r < Nw) ? 16 : 0;
        bsrc[j] = Wk + (size_t)min(bn + r, Nw - 1) * K + kcol;
        bdst[j] = sbB + (uint32_t)((r * S + kcol) << 2);
    }
    constexpr uint32_t ASTGB = ASTG * 4, BSTGB = BSTG * 4;

    auto issue = [&](int st, int k0) {
        #pragma unroll
        for (int j = 0; j < AJ; j++) cpa16(adst[j] + st * ASTGB, asrc[j] + k0, 16);
        #pragma unroll
        for (int j = 0; j < BJ; j++) cpa16(bdst[j] + st * BSTGB, bsrc[j] + k0, bval[j]);
        CP_COMMIT();
    };

    issue(0, 0);
    issue(1, 16);
    issue(2, 32);

    const int fa_base = (wm * 64 + lr) * S + lc;
    const int fb_base = (wn * 64 + lr) * S + lc;

    for (int ks = 0; ks < NS; ks++) {
        const int buf = ks & 3;
        CP_WAIT2();
        __syncthreads();

        if (ks + 3 < NS) issue((ks + 3) & 3, (ks + 3) << 4);
        else CP_COMMIT();

        const uint32_t* Asb = (const uint32_t*)(As + buf * ASTG);
        const uint32_t* Bsb = (const uint32_t*)(Bs + buf * BSTG);

        #pragma unroll
        for (int kc = 0; kc < 2; kc++) {
            uint32_t af[MT][4], bf[NT][2];
            #pragma unroll
            for (int tm = 0; tm < MT; tm++) {
                const int base = fa_base + tm * 16 * S + kc * 8;
                af[tm][0] = Asb[base];
                af[tm][1] = Asb[base + 8 * S];
                af[tm][2] = Asb[base + 4];
                af[tm][3] = Asb[base + 8 * S + 4];
            }
            #pragma unroll
            for (int tn = 0; tn < NT; tn++) {
                const int base = fb_base + tn * 8 * S + kc * 8;
                bf[tn][0] = Bsb[base];
                bf[tn][1] = Bsb[base + 4];
            }
            #pragma unroll
            for (int tm = 0; tm < MT; tm++)
                #pragma unroll
                for (int tn = 0; tn < NT; tn++)
                    mma_tf32(acc[tm][tn], af[tm][0], af[tm][1], af[tm][2], af[tm][3],
                             bf[tn][0], bf[tn][1]);
        }
    }

    // Epilogue
    if (isbc) {
        #pragma unroll
        for (int tm = 0; tm < MT; tm++) {
            const int row = bm + wm * 64 + tm * 16 + lr;
            #pragma unroll
            for (int tn = 0; tn < NT; tn++) {
                const int col = wn * 64 + tn * 8 + lc * 2;
                if (col < 32) {
                    *(float2*)(C2 + (size_t)row * 32 + col) =
                        make_float2(acc[tm][tn][0] * CBIAS, acc[tm][tn][1] * CBIAS);
                    *(float2*)(C2 + (size_t)(row + 8) * 32 + col) =
                        make_float2(acc[tm][tn][2] * CBIAS, acc[tm][tn][3] * CBIAS);
                }
            }
        }
        return;
    }

    #pragma unroll
    for (int tm = 0; tm < MT; tm++) {
        const int row = bm + wm * 64 + tm * 16 + lr;
        #pragma unroll
        for (int tn = 0; tn < NT; tn++) {
            const int col = bn + wn * 64 + tn * 8 + lc * 2;
            if (col < N) {
                const size_t o0 = (size_t)row * N + col;
                const size_t o1 = (size_t)(row + 8) * N + col;
                float2 v0 = make_float2(acc[tm][tn][0] * CBIAS, acc[tm][tn][1] * CBIAS);
                float2 v1 = make_float2(acc[tm][tn][2] * CBIAS, acc[tm][tn][3] * CBIAS);
                if (EP == EP_ADD) {
                    const float2 r0 = *(const float2*)(R + o0);
                    const float2 r1 = *(const float2*)(R + o1);
                    v0.x += r0.x; v0.y += r0.y; v1.x += r1.x; v1.y += r1.y;
                } else if (EP == EP_GATEMUL) {
                    const float2 r0 = *(const float2*)(R + o0);
                    const float2 r1 = *(const float2*)(R + o1);
                    v0.x = r0.x * sigm(v0.x); v0.y = r0.y * sigm(v0.y);
                    v1.x = r1.x * sigm(v1.x); v1.y = r1.y * sigm(v1.y);
                } else if (EP == EP_SOFTPLUS) {
                    const float2 bv = *(const float2*)(bias + col);
                    v0.x = sftp(v0.x + bv.x); v0.y = sftp(v0.y + bv.y);
                    v1.x = sftp(v1.x + bv.x); v1.y = sftp(v1.y + bv.y);
                } else if (EP == EP_SILUMUL) {
                    const float2 r0 = *(const float2*)(R + o0);
                    const float2 r1 = *(const float2*)(R + o1);
                    v0.x = r0.x * sigm(r0.x) * v0.x; v0.y = r0.y * sigm(r0.y) * v0.y;
                    v1.x = r1.x * sigm(r1.x) * v1.x; v1.y = r1.y * sigm(r1.y) * v1.y;
                }
                *(float2*)(C + o0) = v0;
                *(float2*)(C + o1) = v1;
            }
        }
    }
}

// ---------------------------------------------------------------------------
// RMSNorm
// ---------------------------------------------------------------------------
__global__ void __launch_bounds__(256) rmsnorm_kernel(
    const float* __restrict__ x, const float* __restrict__ w, float* __restrict__ out)
{
    __shared__ float red[8];
    const int row = blockIdx.x;
    const int tid = threadIdx.x;
    const float4 v = ((const float4*)(x + (size_t)row * DM))[tid];
    float s = v.x*v.x + v.y*v.y + v.z*v.z + v.w*v.w;
    #pragma unroll
    for (int o = 16; o; o >>= 1) s += __shfl_xor_sync(0xffffffffu, s, o);
    if ((tid & 31) == 0) red[tid >> 5] = s;
    __syncthreads();
    if (tid < 8) {
        float t = red[tid];
        #pragma unroll
        for (int o = 4; o; o >>= 1) t += __shfl_xor_sync(0xffu, t, o);
        if (tid == 0) red[0] = t;
    }
    __syncthreads();
    const float scale = rsqrtf(red[0] * (1.0f / DM) + 1e-6f);
    const float4 wv = ((const float4*)w)[tid];
    float4 o4;
    o4.x = v.x * scale * wv.x; o4.y = v.y * scale * wv.y;
    o4.z = v.z * scale * wv.z; o4.w = v.w * scale * wv.w;
    ((float4*)(out + (size_t)row * DM))[tid] = o4;
}

// ---------------------------------------------------------------------------
// Selective scan (16 lanes per channel)
// ---------------------------------------------------------------------------
__global__ void __launch_bounds__(256) scan_kernel(
    const float* __restrict__ A_log, const float* __restrict__ Dp)
{
    const int tid = threadIdx.x;
    const int ch  = blockIdx.x * 16 + (tid >> 4);
    const int n   = tid & 15;
    const int b   = ch / DIN;
    const int e   = ch % DIN;

    const float An  = -__expf(A_log[(size_t)e * NST + n]);
    const float dpe = Dp[e];

    const float* dtp = g_b  + (size_t)b * SEQ * DIN + e;
    const float* zp  = g_a  + (size_t)b * SEQ * DIN + e;
    const float* bcp = g_bc + (size_t)b * SEQ * 32;
    float*       yp  = g_y  + (size_t)b * SEQ * DIN + e;

    float state = 0.0f;
    #pragma unroll 4
    for (int t = 0; t < SEQ; t++) {
        const float dtv = __ldg(dtp + (size_t)t * DIN);
        const float zv  = __ldg(zp  + (size_t)t * DIN);
        const float Bn  = bcp[t * 32 + n];
        const float Cn  = bcp[t * 32 + 16 + n];
        state = __expf(dtv * An) * state + dtv * zv * Bn;
        float s = state * Cn;
        s += __shfl_xor_sync(0xffffffffu, s, 8);
        s += __shfl_xor_sync(0xffffffffu, s, 4);
        s += __shfl_xor_sync(0xffffffffu, s, 2);
        s += __shfl_xor_sync(0xffffffffu, s, 1);
        if (n == 0) yp[(size_t)t * DIN] = s + zv * dpe;
    }
}

// ---------------------------------------------------------------------------
// Launch
// ---------------------------------------------------------------------------
extern "C" void kernel_launch(void* const* d_in, const int* in_sizes, int n_in,
                              void* d_out, int out_size)
{
    const float* x          = (const float*)d_in[0];
    const float* norm1_w    = (const float*)d_in[1];
    const float* in_proj_w  = (const float*)d_in[2];
    const float* gate_proj_w= (const float*)d_in[3];
    const float* dt_w       = (const float*)d_in[4];
    const float* dt_b       = (const float*)d_in[5];
    const float* x_proj_w   = (const float*)d_in[6];
    const float* A_log      = (const float*)d_in[7];
    const float* Dp         = (const float*)d_in[8];
    const float* out_proj_w = (const float*)d_in[9];
    const float* ffn_norm_w = (const float*)d_in[10];
    const float* ffn_gate_w = (const float*)d_in[11];
    const float* ffn_up_w   = (const float*)d_in[12];
    const float* ffn_down_w = (const float*)d_in[13];
    float* out = (float*)d_out;

    float *h, *a, *bb, *y, *x2, *gg, *bc;
    cudaGetSymbolAddress((void**)&h,  g_h);
    cudaGetSymbolAddress((void**)&a,  g_a);
    cudaGetSymbolAddress((void**)&bb, g_b);
    cudaGetSymbolAddress((void**)&y,  g_y);
    cudaGetSymbolAddress((void**)&x2, g_x2);
    cudaGetSymbolAddress((void**)&gg, g_g);
    cudaGetSymbolAddress((void**)&bc, g_bc);

    const int SM_BIG = STAGES * (128 + 256) * S * 4;   // 122880
    const int SM_SML = STAGES * (128 + 128) * S * 4;   // 81920

    cudaFuncSetAttribute((const void*)gemm_ca<EP_NONE,256,256>,     cudaFuncAttributeMaxDynamicSharedMemorySize, SM_BIG);
    cudaFuncSetAttribute((const void*)gemm_ca<EP_GATEMUL,256,256>,  cudaFuncAttributeMaxDynamicSharedMemorySize, SM_BIG);
    cudaFuncSetAttribute((const void*)gemm_ca<EP_SOFTPLUS,256,256>, cudaFuncAttributeMaxDynamicSharedMemorySize, SM_BIG);
    cudaFuncSetAttribute((const void*)gemm_ca<EP_SILUMUL,256,256>,  cudaFuncAttributeMaxDynamicSharedMemorySize, SM_BIG);
    cudaFuncSetAttribute((const void*)gemm_ca<EP_ADD,128,128>,      cudaFuncAttributeMaxDynamicSharedMemorySize, SM_SML);

    const dim3 blk256(256), blk128(128);

    // 1. h = rmsnorm(x)
    rmsnorm_kernel<<<ROWS, blk256>>>(x, norm1_w, h);

    // 2. z = h @ in_proj^T ; z *= sigmoid(h @ gate_proj^T)
    gemm_ca<EP_NONE,256,256>   <<<dim3(DIN/256, ROWS/128), blk256, SM_BIG>>>(h, in_proj_w,   nullptr, nullptr, a, ROWS, DIN, DM, nullptr, nullptr);
    gemm_ca<EP_GATEMUL,256,256><<<dim3(DIN/256, ROWS/128), blk256, SM_BIG>>>(h, gate_proj_w, a,       nullptr, a, ROWS, DIN, DM, nullptr, nullptr);

    // 3. dt = softplus(z @ dt_w^T + dt_b)  [+ folded BC = z @ x_proj^T]
    gemm_ca<EP_SOFTPLUS,256,256><<<dim3(DIN/256 + 1, ROWS/128), blk256, SM_BIG>>>(a, dt_w, nullptr, dt_b, bb, ROWS, DIN, DIN, x_proj_w, bc);

    // 4. scan
    scan_kernel<<<(BATCH * DIN) / 16, blk256>>>(A_log, Dp);

    // 5. x2 = x + y @ out_proj^T
    gemm_ca<EP_ADD,128,128><<<dim3(DM/128, ROWS/128), blk128, SM_SML>>>(y, out_proj_w, x, nullptr, x2, ROWS, DM, DIN, nullptr, nullptr);

    // 6. hn = rmsnorm(x2)
    rmsnorm_kernel<<<ROWS, blk256>>>(x2, ffn_norm_w, h);

    // 7. FFN: gg = silu(hn @ Wg^T) * (hn @ Wu^T)
    gemm_ca<EP_NONE,256,256>   <<<dim3((FH+255)/256, ROWS/128), blk256, SM_BIG>>>(h, ffn_gate_w, nullptr, nullptr, gg, ROWS, FH, DM, nullptr, nullptr);
    gemm_ca<EP_SILUMUL,256,256><<<dim3((FH+255)/256, ROWS/128), blk256, SM_BIG>>>(h, ffn_up_w,   gg,      nullptr, gg, ROWS, FH, DM, nullptr, nullptr);

    // 8. out = x2 + gg @ Wd^T
    gemm_ca<EP_ADD,128,128><<<dim3(DM/128, ROWS/128), blk128, SM_SML>>>(gg, ffn_down_w, x2, nullptr, out, ROWS, DM, FH, nullptr, nullptr);
}

// round 8
// speedup vs baseline: 1.1079x; 1.1079x over previous
#include <cuda_runtime.h>
#include <math.h>
#include <stdint.h>

// Problem dims
constexpr int BATCH = 2;
constexpr int SEQ   = 1024;
constexpr int DM    = 1024;
constexpr int DIN   = 2048;
constexpr int NST   = 16;
constexpr int FH    = 2752;
constexpr int ROWS  = BATCH * SEQ;  // 2048

// Scratch
__device__ float g_h [ROWS * DM];
__device__ float g_a [ROWS * DIN];
__device__ float g_b [ROWS * DIN];
__device__ float g_y [ROWS * DIN];
__device__ float g_x2[ROWS * DM];
__device__ float g_bc[ROWS * 2 * NST];
__device__ float g_g [ROWS * FH];

constexpr int S = 20;            // smem row stride (floats), conflict-free
constexpr int STAGES = 4;
constexpr float CBIAS = 1.00048828125f;   // 1 + 2^-11 tf32-truncation compensation

__device__ __forceinline__ uint32_t s2u(const void* p) {
    uint32_t a;
    asm("{ .reg .u64 t; cvta.to.shared.u64 t, %1; cvt.u32.u64 %0, t; }" : "=r"(a) : "l"(p));
    return a;
}
__device__ __forceinline__ void cpa16(uint32_t dst, const float* src, int szbytes) {
    asm volatile("cp.async.cg.shared.global [%0], [%1], 16, %2;"
                 :: "r"(dst), "l"(src), "r"(szbytes));
}
#define CP_COMMIT() asm volatile("cp.async.commit_group;" ::: "memory")
#define CP_WAIT2()  asm volatile("cp.async.wait_group 2;" ::: "memory")

__device__ __forceinline__ void mma_tf32(float c[4],
                                         uint32_t a0, uint32_t a1, uint32_t a2, uint32_t a3,
                                         uint32_t b0, uint32_t b1) {
    asm volatile(
        "mma.sync.aligned.m16n8k8.row.col.f32.tf32.tf32.f32 "
        "{%0,%1,%2,%3}, {%4,%5,%6,%7}, {%8,%9}, {%0,%1,%2,%3};"
        : "+f"(c[0]), "+f"(c[1]), "+f"(c[2]), "+f"(c[3])
        : "r"(a0), "r"(a1), "r"(a2), "r"(a3), "r"(b0), "r"(b1));
}

enum { EP_NONE = 0, EP_ADD, EP_GATEMUL, EP_SOFTPLUS, EP_SILUMUL };

__device__ __forceinline__ float sigm(float x) { return 1.0f / (1.0f + expf(-x)); }
__device__ __forceinline__ float sftp(float x) { return (x > 20.0f) ? x : log1pf(expf(x)); }

// ---------------------------------------------------------------------------
// tf32 GEMM: BM=BN=128, 128 threads (4 warps, 2x2), warp tile 64x64
// (MT=4, NT=8).  bytes/MMA = 128 (crossbar ceiling ~59% tensor).
// 2 CTAs/SM (reg budget: ~210 x 128 x 2 = 54K < 64K) so one CTA's MMAs
// cover the other's barrier/cp.async bubbles.  4-stage cp.async pipeline.
// Optional folded side-block (last blockIdx.x): C2 = A @ W2^T, N2=32.
// ---------------------------------------------------------------------------
template<int EP>
__global__ void __launch_bounds__(128, 2) gemm_ca(
    const float* __restrict__ A, const float* __restrict__ W,
    const float* __restrict__ R, const float* __restrict__ bias,
    float* __restrict__ C, int M, int N, int K,
    const float* __restrict__ W2, float* __restrict__ C2)
{
    constexpr int MT = 4, NT = 8;
    constexpr int ASTG = 128 * S;            // floats per stage (each matrix)

    extern __shared__ float sm[];
    float* As = sm;
    float* Bs = sm + STAGES * ASTG;
    const uint32_t sbA = s2u(As), sbB = s2u(Bs);

    const int tid  = threadIdx.x;
    const int wid  = tid >> 5, lane = tid & 31;
    const int wm   = wid >> 1, wn = wid & 1;
    const int bm   = blockIdx.y << 7;
    const int bx   = blockIdx.x;
    const bool isbc = (W2 != nullptr) && (bx == (int)gridDim.x - 1);
    const int bn   = isbc ? 0 : (bx << 7);
    const int Nw   = isbc ? 32 : N;
    const float* Wk = isbc ? W2 : W;
    const int lr   = lane >> 2, lc = lane & 3;

    float acc[MT][NT][4];
    #pragma unroll
    for (int i = 0; i < MT; i++)
        #pragma unroll
        for (int j = 0; j < NT; j++)
            #pragma unroll
            for (int q = 0; q < 4; q++) acc[i][j][q] = 0.0f;

    const int row0 = tid >> 2;               // +32 per j (4 steps cover 128 rows)
    const int kcol = (tid & 3) << 2;
    const int NS   = K >> 4;

    const float* asrc[4];
    const float* bsrc[4];
    uint32_t adst[4], bdst[4];
    int bval[4];
    #pragma unroll
    for (int j = 0; j < 4; j++) {
        const int r = row0 + 32 * j;
        asrc[j] = A + (size_t)(bm + r) * K + kcol;
        adst[j] = sbA + (uint32_t)((r * S + kcol) << 2);
        bval[j] = (bn + r < Nw) ? 16 : 0;
        bsrc[j] = Wk + (size_t)min(bn + r, Nw - 1) * K + kcol;
        bdst[j] = sbB + (uint32_t)((r * S + kcol) << 2);
    }
    constexpr uint32_t STGB = ASTG * 4;

    auto issue = [&](int st, int k0) {
        #pragma unroll
        for (int j = 0; j < 4; j++) cpa16(adst[j] + st * STGB, asrc[j] + k0, 16);
        #pragma unroll
        for (int j = 0; j < 4; j++) cpa16(bdst[j] + st * STGB, bsrc[j] + k0, bval[j]);
        CP_COMMIT();
    };

    issue(0, 0);
    issue(1, 16);
    issue(2, 32);

    const int fa_base = (wm * 64 + lr) * S + lc;
    const int fb_base = (wn * 64 + lr) * S + lc;

    for (int ks = 0; ks < NS; ks++) {
        const int buf = ks & 3;
        CP_WAIT2();
        __syncthreads();

        if (ks + 3 < NS) issue((ks + 3) & 3, (ks + 3) << 4);
        else CP_COMMIT();

        const uint32_t* Asb = (const uint32_t*)(As + buf * ASTG);
        const uint32_t* Bsb = (const uint32_t*)(Bs + buf * ASTG);

        #pragma unroll
        for (int kc = 0; kc < 2; kc++) {
            uint32_t af[MT][4], bf[NT][2];
            #pragma unroll
            for (int tm = 0; tm < MT; tm++) {
                const int base = fa_base + tm * 16 * S + kc * 8;
                af[tm][0] = Asb[base];
                af[tm][1] = Asb[base + 8 * S];
                af[tm][2] = Asb[base + 4];
                af[tm][3] = Asb[base + 8 * S + 4];
            }
            #pragma unroll
            for (int tn = 0; tn < NT; tn++) {
                const int base = fb_base + tn * 8 * S + kc * 8;
                bf[tn][0] = Bsb[base];
                bf[tn][1] = Bsb[base + 4];
            }
            #pragma unroll
            for (int tm = 0; tm < MT; tm++)
                #pragma unroll
                for (int tn = 0; tn < NT; tn++)
                    mma_tf32(acc[tm][tn], af[tm][0], af[tm][1], af[tm][2], af[tm][3],
                             bf[tn][0], bf[tn][1]);
        }
    }

    // Epilogue (CBIAS compensates tf32 truncation bias)
    if (isbc) {
        #pragma unroll
        for (int tm = 0; tm < MT; tm++) {
            const int row = bm + wm * 64 + tm * 16 + lr;
            #pragma unroll
            for (int tn = 0; tn < NT; tn++) {
                const int col = wn * 64 + tn * 8 + lc * 2;
                if (col < 32) {
                    *(float2*)(C2 + (size_t)row * 32 + col) =
                        make_float2(acc[tm][tn][0] * CBIAS, acc[tm][tn][1] * CBIAS);
                    *(float2*)(C2 + (size_t)(row + 8) * 32 + col) =
                        make_float2(acc[tm][tn][2] * CBIAS, acc[tm][tn][3] * CBIAS);
                }
            }
        }
        return;
    }

    #pragma unroll
    for (int tm = 0; tm < MT; tm++) {
        const int row = bm + wm * 64 + tm * 16 + lr;
        #pragma unroll
        for (int tn = 0; tn < NT; tn++) {
            const int col = bn + wn * 64 + tn * 8 + lc * 2;
            if (col < N) {
                const size_t o0 = (size_t)row * N + col;
                const size_t o1 = (size_t)(row + 8) * N + col;
                float2 v0 = make_float2(acc[tm][tn][0] * CBIAS, acc[tm][tn][1] * CBIAS);
                float2 v1 = make_float2(acc[tm][tn][2] * CBIAS, acc[tm][tn][3] * CBIAS);
                if (EP == EP_ADD) {
                    const float2 r0 = *(const float2*)(R + o0);
                    const float2 r1 = *(const float2*)(R + o1);
                    v0.x += r0.x; v0.y += r0.y; v1.x += r1.x; v1.y += r1.y;
                } else if (EP == EP_GATEMUL) {
                    const float2 r0 = *(const float2*)(R + o0);
                    const float2 r1 = *(const float2*)(R + o1);
                    v0.x = r0.x * sigm(v0.x); v0.y = r0.y * sigm(v0.y);
                    v1.x = r1.x * sigm(v1.x); v1.y = r1.y * sigm(v1.y);
                } else if (EP == EP_SOFTPLUS) {
                    const float2 bv = *(const float2*)(bias + col);
                    v0.x = sftp(v0.x + bv.x); v0.y = sftp(v0.y + bv.y);
                    v1.x = sftp(v1.x + bv.x); v1.y = sftp(v1.y + bv.y);
                } else if (EP == EP_SILUMUL) {
                    const float2 r0 = *(const float2*)(R + o0);
                    const float2 r1 = *(const float2*)(R + o1);
                    v0.x = r0.x * sigm(r0.x) * v0.x; v0.y = r0.y * sigm(r0.y) * v0.y;
                    v1.x = r1.x * sigm(r1.x) * v1.x; v1.y = r1.y * sigm(r1.y) * v1.y;
                }
                *(float2*)(C + o0) = v0;
                *(float2*)(C + o1) = v1;
            }
        }
    }
}

// ---------------------------------------------------------------------------
// RMSNorm
// ---------------------------------------------------------------------------
__global__ void __launch_bounds__(256) rmsnorm_kernel(
    const float* __restrict__ x, const float* __restrict__ w, float* __restrict__ out)
{
    __shared__ float red[8];
    const int row = blockIdx.x;
    const int tid = threadIdx.x;
    const float4 v = ((const float4*)(x + (size_t)row * DM))[tid];
    float s = v.x*v.x + v.y*v.y + v.z*v.z + v.w*v.w;
    #pragma unroll
    for (int o = 16; o; o >>= 1) s += __shfl_xor_sync(0xffffffffu, s, o);
    if ((tid & 31) == 0) red[tid >> 5] = s;
    __syncthreads();
    if (tid < 8) {
        float t = red[tid];
        #pragma unroll
        for (int o = 4; o; o >>= 1) t += __shfl_xor_sync(0xffu, t, o);
        if (tid == 0) red[0] = t;
    }
    __syncthreads();
    const float scale = rsqrtf(red[0] * (1.0f / DM) + 1e-6f);
    const float4 wv = ((const float4*)w)[tid];
    float4 o4;
    o4.x = v.x * scale * wv.x; o4.y = v.y * scale * wv.y;
    o4.z = v.z * scale * wv.z; o4.w = v.w * scale * wv.w;
    ((float4*)(out + (size_t)row * DM))[tid] = o4;
}

// ---------------------------------------------------------------------------
// Selective scan (16 lanes per channel)
// ---------------------------------------------------------------------------
__global__ void __launch_bounds__(256) scan_kernel(
    const float* __restrict__ A_log, const float* __restrict__ Dp)
{
    const int tid = threadIdx.x;
    const int ch  = blockIdx.x * 16 + (tid >> 4);
    const int n   = tid & 15;
    const int b   = ch / DIN;
    const int e   = ch % DIN;

    const float An  = -__expf(A_log[(size_t)e * NST + n]);
    const float dpe = Dp[e];

    const float* dtp = g_b  + (size_t)b * SEQ * DIN + e;
    const float* zp  = g_a  + (size_t)b * SEQ * DIN + e;
    const float* bcp = g_bc + (size_t)b * SEQ * 32;
    float*       yp  = g_y  + (size_t)b * SEQ * DIN + e;

    float state = 0.0f;
    #pragma unroll 4
    for (int t = 0; t < SEQ; t++) {
        const float dtv = __ldg(dtp + (size_t)t * DIN);
        const float zv  = __ldg(zp  + (size_t)t * DIN);
        const float Bn  = bcp[t * 32 + n];
        const float Cn  = bcp[t * 32 + 16 + n];
        state = __expf(dtv * An) * state + dtv * zv * Bn;
        float s = state * Cn;
        s += __shfl_xor_sync(0xffffffffu, s, 8);
        s += __shfl_xor_sync(0xffffffffu, s, 4);
        s += __shfl_xor_sync(0xffffffffu, s, 2);
        s += __shfl_xor_sync(0xffffffffu, s, 1);
        if (n == 0) yp[(size_t)t * DIN] = s + zv * dpe;
    }
}

// ---------------------------------------------------------------------------
// Launch
// ---------------------------------------------------------------------------
extern "C" void kernel_launch(void* const* d_in, const int* in_sizes, int n_in,
                              void* d_out, int out_size)
{
    const float* x          = (const float*)d_in[0];
    const float* norm1_w    = (const float*)d_in[1];
    const float* in_proj_w  = (const float*)d_in[2];
    const float* gate_proj_w= (const float*)d_in[3];
    const float* dt_w       = (const float*)d_in[4];
    const float* dt_b       = (const float*)d_in[5];
    const float* x_proj_w   = (const float*)d_in[6];
    const float* A_log      = (const float*)d_in[7];
    const float* Dp         = (const float*)d_in[8];
    const float* out_proj_w = (const float*)d_in[9];
    const float* ffn_norm_w = (const float*)d_in[10];
    const float* ffn_gate_w = (const float*)d_in[11];
    const float* ffn_up_w   = (const float*)d_in[12];
    const float* ffn_down_w = (const float*)d_in[13];
    float* out = (float*)d_out;

    float *h, *a, *bb, *y, *x2, *gg, *bc;
    cudaGetSymbolAddress((void**)&h,  g_h);
    cudaGetSymbolAddress((void**)&a,  g_a);
    cudaGetSymbolAddress((void**)&bb, g_b);
    cudaGetSymbolAddress((void**)&y,  g_y);
    cudaGetSymbolAddress((void**)&x2, g_x2);
    cudaGetSymbolAddress((void**)&gg, g_g);
    cudaGetSymbolAddress((void**)&bc, g_bc);

    const int SMEM = STAGES * (128 + 128) * S * 4;   // 81920 bytes

    cudaFuncSetAttribute((const void*)gemm_ca<EP_NONE>,     cudaFuncAttributeMaxDynamicSharedMemorySize, SMEM);
    cudaFuncSetAttribute((const void*)gemm_ca<EP_ADD>,      cudaFuncAttributeMaxDynamicSharedMemorySize, SMEM);
    cudaFuncSetAttribute((const void*)gemm_ca<EP_GATEMUL>,  cudaFuncAttributeMaxDynamicSharedMemorySize, SMEM);
    cudaFuncSetAttribute((const void*)gemm_ca<EP_SOFTPLUS>, cudaFuncAttributeMaxDynamicSharedMemorySize, SMEM);
    cudaFuncSetAttribute((const void*)gemm_ca<EP_SILUMUL>,  cudaFuncAttributeMaxDynamicSharedMemorySize, SMEM);

    const dim3 blk256(256), blk128(128);

    // 1. h = rmsnorm(x)
    rmsnorm_kernel<<<ROWS, blk256>>>(x, norm1_w, h);

    // 2. z = h @ in_proj^T ; z *= sigmoid(h @ gate_proj^T)
    gemm_ca<EP_NONE>   <<<dim3(DIN/128, ROWS/128), blk128, SMEM>>>(h, in_proj_w,   nullptr, nullptr, a, ROWS, DIN, DM, nullptr, nullptr);
    gemm_ca<EP_GATEMUL><<<dim3(DIN/128, ROWS/128), blk128, SMEM>>>(h, gate_proj_w, a,       nullptr, a, ROWS, DIN, DM, nullptr, nullptr);

    // 3. dt = softplus(z @ dt_w^T + dt_b)  [+ folded BC = z @ x_proj^T]
    gemm_ca<EP_SOFTPLUS><<<dim3(DIN/128 + 1, ROWS/128), blk128, SMEM>>>(a, dt_w, nullptr, dt_b, bb, ROWS, DIN, DIN, x_proj_w, bc);

    // 4. scan
    scan_kernel<<<(BATCH * DIN) / 16, blk256>>>(A_log, Dp);

    // 5. x2 = x + y @ out_proj^T
    gemm_ca<EP_ADD><<<dim3(DM/128, ROWS/128), blk128, SMEM>>>(y, out_proj_w, x, nullptr, x2, ROWS, DM, DIN, nullptr, nullptr);

    // 6. hn = rmsnorm(x2)
    rmsnorm_kernel<<<ROWS, blk256>>>(x2, ffn_norm_w, h);

    // 7. FFN: gg = silu(hn @ Wg^T) * (hn @ Wu^T)
    gemm_ca<EP_NONE>   <<<dim3((FH+127)/128, ROWS/128), blk128, SMEM>>>(h, ffn_gate_w, nullptr, nullptr, gg, ROWS, FH, DM, nullptr, nullptr);
    gemm_ca<EP_SILUMUL><<<dim3((FH+127)/128, ROWS/128), blk128, SMEM>>>(h, ffn_up_w,   gg,      nullptr, gg, ROWS, FH, DM, nullptr, nullptr);

    // 8. out = x2 + gg @ Wd^T
    gemm_ca<EP_ADD><<<dim3(DM/128, ROWS/128), blk128, SMEM>>>(gg, ffn_down_w, x2, nullptr, out, ROWS, DM, FH, nullptr, nullptr);
}

// round 9
// speedup vs baseline: 1.1435x; 1.0321x over previous
#include <cuda_runtime.h>
#include <math.h>
#include <stdint.h>

// Problem dims
constexpr int BATCH = 2;
constexpr int SEQ   = 1024;
constexpr int DM    = 1024;
constexpr int DIN   = 2048;
constexpr int NST   = 16;
constexpr int FH    = 2752;
constexpr int ROWS  = BATCH * SEQ;  // 2048

// Scratch
__device__ float g_h [ROWS * DM];
__device__ float g_a [ROWS * DIN];
__device__ float g_b [ROWS * DIN];
__device__ float g_y [ROWS * DIN];
__device__ float g_x2[ROWS * DM];
__device__ float g_bc[ROWS * 2 * NST];
__device__ float g_g [ROWS * FH];
__device__ float g_p0[ROWS * DM];   // K-split partials
__device__ float g_p1[ROWS * DM];

constexpr int S = 20;            // smem row stride (floats), conflict-free
constexpr int STAGES = 4;
constexpr float CBIAS = 1.00048828125f;   // 1 + 2^-11 tf32-truncation compensation

__device__ __forceinline__ uint32_t s2u(const void* p) {
    uint32_t a;
    asm("{ .reg .u64 t; cvta.to.shared.u64 t, %1; cvt.u32.u64 %0, t; }" : "=r"(a) : "l"(p));
    return a;
}
__device__ __forceinline__ void cpa16(uint32_t dst, const float* src, int szbytes) {
    asm volatile("cp.async.cg.shared.global [%0], [%1], 16, %2;"
                 :: "r"(dst), "l"(src), "r"(szbytes));
}
#define CP_COMMIT() asm volatile("cp.async.commit_group;" ::: "memory")
#define CP_WAIT2()  asm volatile("cp.async.wait_group 2;" ::: "memory")

__device__ __forceinline__ void mma_tf32(float c[4],
                                         uint32_t a0, uint32_t a1, uint32_t a2, uint32_t a3,
                                         uint32_t b0, uint32_t b1) {
    asm volatile(
        "mma.sync.aligned.m16n8k8.row.col.f32.tf32.tf32.f32 "
        "{%0,%1,%2,%3}, {%4,%5,%6,%7}, {%8,%9}, {%0,%1,%2,%3};"
        : "+f"(c[0]), "+f"(c[1]), "+f"(c[2]), "+f"(c[3])
        : "r"(a0), "r"(a1), "r"(a2), "r"(a3), "r"(b0), "r"(b1));
}

enum { EP_NONE = 0, EP_ADD, EP_GATEMUL, EP_SOFTPLUS, EP_SILUMUL };

__device__ __forceinline__ float sigm(float x) { return 1.0f / (1.0f + expf(-x)); }
__device__ __forceinline__ float sftp(float x) { return (x > 20.0f) ? x : log1pf(expf(x)); }

// ---------------------------------------------------------------------------
// tf32 GEMM: BM=BN=128, 128 threads (4 warps 2x2), warp tile 64x64.
// 4-stage cp.async, 2 CTAs/SM.  lda/ldw = leading dims (row strides of A/W).
// K = K-extent THIS CTA processes.  If P1 != nullptr: K-split mode, CTA z=1
// reads A/W at column offset K and writes partial P1 (z=0 writes C).
// Optional folded side-block (last blockIdx.x, W2 != nullptr): C2 = A@W2^T, N2=32.
// ---------------------------------------------------------------------------
template<int EP>
__global__ void __launch_bounds__(128, 2) gemm_ca(
    const float* __restrict__ A, const float* __restrict__ W,
    const float* __restrict__ R, const float* __restrict__ bias,
    float* __restrict__ C, int M, int N, int K, int lda, int ldw,
    const float* __restrict__ W2, float* __restrict__ C2,
    float* __restrict__ P1)
{
    constexpr int MT = 4, NT = 8;
    constexpr int ASTG = 128 * S;

    extern __shared__ float sm[];
    float* As = sm;
    float* Bs = sm + STAGES * ASTG;
    const uint32_t sbA = s2u(As), sbB = s2u(Bs);

    const int tid  = threadIdx.x;
    const int wid  = tid >> 5, lane = tid & 31;
    const int wm   = wid >> 1, wn = wid & 1;
    const int bm   = blockIdx.y << 7;
    const int bx   = blockIdx.x;
    const int bz   = blockIdx.z;
    const int koff = bz * K;                 // K-split column offset
    float* Cw      = (P1 != nullptr && bz == 1) ? P1 : C;
    const bool isbc = (W2 != nullptr) && (bx == (int)gridDim.x - 1);
    const int bn   = isbc ? 0 : (bx << 7);
    const int Nw   = isbc ? 32 : N;
    const float* Wk = isbc ? W2 : W;
    const int lr   = lane >> 2, lc = lane & 3;

    float acc[MT][NT][4];
    #pragma unroll
    for (int i = 0; i < MT; i++)
        #pragma unroll
        for (int j = 0; j < NT; j++)
            #pragma unroll
            for (int q = 0; q < 4; q++) acc[i][j][q] = 0.0f;

    const int row0 = tid >> 2;
    const int kcol = (tid & 3) << 2;
    const int NS   = K >> 4;

    const float* asrc[4];
    const float* bsrc[4];
    uint32_t adst[4], bdst[4];
    int bval[4];
    #pragma unroll
    for (int j = 0; j < 4; j++) {
        const int r = row0 + 32 * j;
        asrc[j] = A + (size_t)(bm + r) * lda + koff + kcol;
        adst[j] = sbA + (uint32_t)((r * S + kcol) << 2);
        bval[j] = (bn + r < Nw) ? 16 : 0;
        bsrc[j] = Wk + (size_t)min(bn + r, Nw - 1) * ldw + koff + kcol;
        bdst[j] = sbB + (uint32_t)((r * S + kcol) << 2);
    }
    constexpr uint32_t STGB = ASTG * 4;

    auto issue = [&](int st, int k0) {
        #pragma unroll
        for (int j = 0; j < 4; j++) cpa16(adst[j] + st * STGB, asrc[j] + k0, 16);
        #pragma unroll
        for (int j = 0; j < 4; j++) cpa16(bdst[j] + st * STGB, bsrc[j] + k0, bval[j]);
        CP_COMMIT();
    };

    issue(0, 0);
    issue(1, 16);
    issue(2, 32);

    const int fa_base = (wm * 64 + lr) * S + lc;
    const int fb_base = (wn * 64 + lr) * S + lc;

    for (int ks = 0; ks < NS; ks++) {
        const int buf = ks & 3;
        CP_WAIT2();
        __syncthreads();

        if (ks + 3 < NS) issue((ks + 3) & 3, (ks + 3) << 4);
        else CP_COMMIT();

        const uint32_t* Asb = (const uint32_t*)(As + buf * ASTG);
        const uint32_t* Bsb = (const uint32_t*)(Bs + buf * ASTG);

        #pragma unroll
        for (int kc = 0; kc < 2; kc++) {
            uint32_t af[MT][4], bf[NT][2];
            #pragma unroll
            for (int tm = 0; tm < MT; tm++) {
                const int base = fa_base + tm * 16 * S + kc * 8;
                af[tm][0] = Asb[base];
                af[tm][1] = Asb[base + 8 * S];
                af[tm][2] = Asb[base + 4];
                af[tm][3] = Asb[base + 8 * S + 4];
            }
            #pragma unroll
            for (int tn = 0; tn < NT; tn++) {
                const int base = fb_base + tn * 8 * S + kc * 8;
                bf[tn][0] = Bsb[base];
                bf[tn][1] = Bsb[base + 4];
            }
            #pragma unroll
            for (int tm = 0; tm < MT; tm++)
                #pragma unroll
                for (int tn = 0; tn < NT; tn++)
                    mma_tf32(acc[tm][tn], af[tm][0], af[tm][1], af[tm][2], af[tm][3],
                             bf[tn][0], bf[tn][1]);
        }
    }

    // Epilogue (CBIAS compensates tf32 truncation bias)
    if (isbc) {
        #pragma unroll
        for (int tm = 0; tm < MT; tm++) {
            const int row = bm + wm * 64 + tm * 16 + lr;
            #pragma unroll
            for (int tn = 0; tn < NT; tn++) {
                const int col = wn * 64 + tn * 8 + lc * 2;
                if (col < 32) {
                    *(float2*)(C2 + (size_t)row * 32 + col) =
                        make_float2(acc[tm][tn][0] * CBIAS, acc[tm][tn][1] * CBIAS);
                    *(float2*)(C2 + (size_t)(row + 8) * 32 + col) =
                        make_float2(acc[tm][tn][2] * CBIAS, acc[tm][tn][3] * CBIAS);
                }
            }
        }
        return;
    }

    #pragma unroll
    for (int tm = 0; tm < MT; tm++) {
        const int row = bm + wm * 64 + tm * 16 + lr;
        #pragma unroll
        for (int tn = 0; tn < NT; tn++) {
            const int col = bn + wn * 64 + tn * 8 + lc * 2;
            if (col < N) {
                const size_t o0 = (size_t)row * N + col;
                const size_t o1 = (size_t)(row + 8) * N + col;
                float2 v0 = make_float2(acc[tm][tn][0] * CBIAS, acc[tm][tn][1] * CBIAS);
                float2 v1 = make_float2(acc[tm][tn][2] * CBIAS, acc[tm][tn][3] * CBIAS);
                if (EP == EP_ADD) {
                    const float2 r0 = *(const float2*)(R + o0);
                    const float2 r1 = *(const float2*)(R + o1);
                    v0.x += r0.x; v0.y += r0.y; v1.x += r1.x; v1.y += r1.y;
                } else if (EP == EP_GATEMUL) {
                    const float2 r0 = *(const float2*)(R + o0);
                    const float2 r1 = *(const float2*)(R + o1);
                    v0.x = r0.x * sigm(v0.x); v0.y = r0.y * sigm(v0.y);
                    v1.x = r1.x * sigm(v1.x); v1.y = r1.y * sigm(v1.y);
                } else if (EP == EP_SOFTPLUS) {
                    const float2 bv = *(const float2*)(bias + col);
                    v0.x = sftp(v0.x + bv.x); v0.y = sftp(v0.y + bv.y);
                    v1.x = sftp(v1.x + bv.x); v1.y = sftp(v1.y + bv.y);
                } else if (EP == EP_SILUMUL) {
                    const float2 r0 = *(const float2*)(R + o0);
                    const float2 r1 = *(const float2*)(R + o1);
                    v0.x = r0.x * sigm(r0.x) * v0.x; v0.y = r0.y * sigm(r0.y) * v0.y;
                    v1.x = r1.x * sigm(r1.x) * v1.x; v1.y = r1.y * sigm(r1.y) * v1.y;
                }
                *(float2*)(Cw + o0) = v0;
                *(float2*)(Cw + o1) = v1;
            }
        }
    }
}

// ---------------------------------------------------------------------------
// RMSNorm
// ---------------------------------------------------------------------------
__global__ void __launch_bounds__(256) rmsnorm_kernel(
    const float* __restrict__ x, const float* __restrict__ w, float* __restrict__ out)
{
    __shared__ float red[8];
    const int row = blockIdx.x;
    const int tid = threadIdx.x;
    const float4 v = ((const float4*)(x + (size_t)row * DM))[tid];
    float s = v.x*v.x + v.y*v.y + v.z*v.z + v.w*v.w;
    #pragma unroll
    for (int o = 16; o; o >>= 1) s += __shfl_xor_sync(0xffffffffu, s, o);
    if ((tid & 31) == 0) red[tid >> 5] = s;
    __syncthreads();
    if (tid < 8) {
        float t = red[tid];
        #pragma unroll
        for (int o = 4; o; o >>= 1) t += __shfl_xor_sync(0xffu, t, o);
        if (tid == 0) red[0] = t;
    }
    __syncthreads();
    const float scale = rsqrtf(red[0] * (1.0f / DM) + 1e-6f);
    const float4 wv = ((const float4*)w)[tid];
    float4 o4;
    o4.x = v.x * scale * wv.x; o4.y = v.y * scale * wv.y;
    o4.z = v.z * scale * wv.z; o4.w = v.w * scale * wv.w;
    ((float4*)(out + (size_t)row * DM))[tid] = o4;
}

// ---------------------------------------------------------------------------
// Combine K-split partials + residual, then RMSNorm:
//   x2 = x + p0 + p1 ;  h = rmsnorm(x2, w)
// ---------------------------------------------------------------------------
__global__ void __launch_bounds__(256) combine_norm_kernel(
    const float* __restrict__ x, const float* __restrict__ w,
    float* __restrict__ x2, float* __restrict__ h)
{
    __shared__ float red[8];
    const int row = blockIdx.x;
    const int tid = threadIdx.x;
    const size_t o = (size_t)row * DM / 4 + tid;
    const float4 xv = ((const float4*)x)[o];
    const float4 p0 = ((const float4*)g_p0)[o];
    const float4 p1 = ((const float4*)g_p1)[o];
    float4 v;
    v.x = xv.x + p0.x + p1.x; v.y = xv.y + p0.y + p1.y;
    v.z = xv.z + p0.z + p1.z; v.w = xv.w + p0.w + p1.w;
    ((float4*)x2)[o] = v;
    float s = v.x*v.x + v.y*v.y + v.z*v.z + v.w*v.w;
    #pragma unroll
    for (int of = 16; of; of >>= 1) s += __shfl_xor_sync(0xffffffffu, s, of);
    if ((tid & 31) == 0) red[tid >> 5] = s;
    __syncthreads();
    if (tid < 8) {
        float t = red[tid];
        #pragma unroll
        for (int of = 4; of; of >>= 1) t += __shfl_xor_sync(0xffu, t, of);
        if (tid == 0) red[0] = t;
    }
    __syncthreads();
    const float scale = rsqrtf(red[0] * (1.0f / DM) + 1e-6f);
    const float4 wv = ((const float4*)w)[tid];
    float4 o4;
    o4.x = v.x * scale * wv.x; o4.y = v.y * scale * wv.y;
    o4.z = v.z * scale * wv.z; o4.w = v.w * scale * wv.w;
    ((float4*)h)[o] = o4;
}

// out = x2 + p0 + p1
__global__ void __launch_bounds__(256) combine_add_kernel(
    const float* __restrict__ x2, float* __restrict__ out)
{
    const size_t i = (size_t)blockIdx.x * 256 + threadIdx.x;
    const float4 a = ((const float4*)x2)[i];
    const float4 p0 = ((const float4*)g_p0)[i];
    const float4 p1 = ((const float4*)g_p1)[i];
    float4 v;
    v.x = a.x + p0.x + p1.x; v.y = a.y + p0.y + p1.y;
    v.z = a.z + p0.z + p1.z; v.w = a.w + p0.w + p1.w;
    ((float4*)out)[i] = v;
}

// ---------------------------------------------------------------------------
// Selective scan (16 lanes per channel)
// ---------------------------------------------------------------------------
__global__ void __launch_bounds__(256) scan_kernel(
    const float* __restrict__ A_log, const float* __restrict__ Dp)
{
    const int tid = threadIdx.x;
    const int ch  = blockIdx.x * 16 + (tid >> 4);
    const int n   = tid & 15;
    const int b   = ch / DIN;
    const int e   = ch % DIN;

    const float An  = -__expf(A_log[(size_t)e * NST + n]);
    const float dpe = Dp[e];

    const float* dtp = g_b  + (size_t)b * SEQ * DIN + e;
    const float* zp  = g_a  + (size_t)b * SEQ * DIN + e;
    const float* bcp = g_bc + (size_t)b * SEQ * 32;
    float*       yp  = g_y  + (size_t)b * SEQ * DIN + e;

    float state = 0.0f;
    #pragma unroll 4
    for (int t = 0; t < SEQ; t++) {
        const float dtv = __ldg(dtp + (size_t)t * DIN);
        const float zv  = __ldg(zp  + (size_t)t * DIN);
        const float Bn  = bcp[t * 32 + n];
        const float Cn  = bcp[t * 32 + 16 + n];
        state = __expf(dtv * An) * state + dtv * zv * Bn;
        float s = state * Cn;
        s += __shfl_xor_sync(0xffffffffu, s, 8);
        s += __shfl_xor_sync(0xffffffffu, s, 4);
        s += __shfl_xor_sync(0xffffffffu, s, 2);
        s += __shfl_xor_sync(0xffffffffu, s, 1);
        if (n == 0) yp[(size_t)t * DIN] = s + zv * dpe;
    }
}

// ---------------------------------------------------------------------------
// Launch
// ---------------------------------------------------------------------------
extern "C" void kernel_launch(void* const* d_in, const int* in_sizes, int n_in,
                              void* d_out, int out_size)
{
    const float* x          = (const float*)d_in[0];
    const float* norm1_w    = (const float*)d_in[1];
    const float* in_proj_w  = (const float*)d_in[2];
    const float* gate_proj_w= (const float*)d_in[3];
    const float* dt_w       = (const float*)d_in[4];
    const float* dt_b       = (const float*)d_in[5];
    const float* x_proj_w   = (const float*)d_in[6];
    const float* A_log      = (const float*)d_in[7];
    const float* Dp         = (const float*)d_in[8];
    const float* out_proj_w = (const float*)d_in[9];
    const float* ffn_norm_w = (const float*)d_in[10];
    const float* ffn_gate_w = (const float*)d_in[11];
    const float* ffn_up_w   = (const float*)d_in[12];
    const float* ffn_down_w = (const float*)d_in[13];
    float* out = (float*)d_out;

    float *h, *a, *bb, *y, *x2, *gg, *bc, *p0, *p1;
    cudaGetSymbolAddress((void**)&h,  g_h);
    cudaGetSymbolAddress((void**)&a,  g_a);
    cudaGetSymbolAddress((void**)&bb, g_b);
    cudaGetSymbolAddress((void**)&y,  g_y);
    cudaGetSymbolAddress((void**)&x2, g_x2);
    cudaGetSymbolAddress((void**)&gg, g_g);
    cudaGetSymbolAddress((void**)&bc, g_bc);
    cudaGetSymbolAddress((void**)&p0, g_p0);
    cudaGetSymbolAddress((void**)&p1, g_p1);

    const int SMEM = STAGES * (128 + 128) * S * 4;   // 81920 bytes

    cudaFuncSetAttribute((const void*)gemm_ca<EP_NONE>,     cudaFuncAttributeMaxDynamicSharedMemorySize, SMEM);
    cudaFuncSetAttribute((const void*)gemm_ca<EP_GATEMUL>,  cudaFuncAttributeMaxDynamicSharedMemorySize, SMEM);
    cudaFuncSetAttribute((const void*)gemm_ca<EP_SOFTPLUS>, cudaFuncAttributeMaxDynamicSharedMemorySize, SMEM);
    cudaFuncSetAttribute((const void*)gemm_ca<EP_SILUMUL>,  cudaFuncAttributeMaxDynamicSharedMemorySize, SMEM);

    const dim3 blk256(256), blk128(128);

    // 1. h = rmsnorm(x)
    rmsnorm_kernel<<<ROWS, blk256>>>(x, norm1_w, h);

    // 2. z = h @ in_proj^T ; z *= sigmoid(h @ gate_proj^T)
    gemm_ca<EP_NONE>   <<<dim3(DIN/128, ROWS/128), blk128, SMEM>>>(h, in_proj_w,   nullptr, nullptr, a, ROWS, DIN, DM, DM, DM, nullptr, nullptr, nullptr);
    gemm_ca<EP_GATEMUL><<<dim3(DIN/128, ROWS/128), blk128, SMEM>>>(h, gate_proj_w, a,       nullptr, a, ROWS, DIN, DM, DM, DM, nullptr, nullptr, nullptr);

    // 3. dt = softplus(z @ dt_w^T + dt_b)  [+ folded BC = z @ x_proj^T]
    gemm_ca<EP_SOFTPLUS><<<dim3(DIN/128 + 1, ROWS/128), blk128, SMEM>>>(a, dt_w, nullptr, dt_b, bb, ROWS, DIN, DIN, DIN, DIN, x_proj_w, bc, nullptr);

    // 4. scan
    scan_kernel<<<(BATCH * DIN) / 16, blk256>>>(A_log, Dp);

    // 5. p0/p1 = y @ out_proj^T (K-split, full machine); x2 = x + p0 + p1 ; h = rmsnorm(x2)
    gemm_ca<EP_NONE><<<dim3(DM/128, ROWS/128, 2), blk128, SMEM>>>(y, out_proj_w, nullptr, nullptr, p0, ROWS, DM, DIN/2, DIN, DIN, nullptr, nullptr, p1);
    combine_norm_kernel<<<ROWS, blk256>>>(x, ffn_norm_w, x2, h);

    // 6. FFN: gg = silu(hn @ Wg^T) * (hn @ Wu^T)
    gemm_ca<EP_NONE>   <<<dim3((FH+127)/128, ROWS/128), blk128, SMEM>>>(h, ffn_gate_w, nullptr, nullptr, gg, ROWS, FH, DM, DM, DM, nullptr, nullptr, nullptr);
    gemm_ca<EP_SILUMUL><<<dim3((FH+127)/128, ROWS/128), blk128, SMEM>>>(h, ffn_up_w,   gg,      nullptr, gg, ROWS, FH, DM, DM, DM, nullptr, nullptr, nullptr);

    // 7. p0/p1 = gg @ Wd^T (K-split); out = x2 + p0 + p1
    gemm_ca<EP_NONE><<<dim3(DM/128, ROWS/128, 2), blk128, SMEM>>>(gg, ffn_down_w, nullptr, nullptr, p0, ROWS, DM, FH/2, FH, FH, nullptr, nullptr, p1);
    combine_add_kernel<<<(ROWS * DM) / 1024, blk256>>>(x2, out);
}

// round 10
// speedup vs baseline: 1.5131x; 1.3232x over previous
#include <cuda_runtime.h>
#include <cuda_fp16.h>
#include <math.h>
#include <stdint.h>

// Problem dims
constexpr int BATCH = 2;
constexpr int SEQ   = 1024;
constexpr int DM    = 1024;
constexpr int DIN   = 2048;
constexpr int NST   = 16;
constexpr int FH    = 2752;
constexpr int ROWS  = BATCH * SEQ;  // 2048

// fp32 scratch
__device__ float g_a [ROWS * DIN];    // z (fp32, for scan)
__device__ float g_b [ROWS * DIN];    // dt
__device__ float g_x2[ROWS * DM];
__device__ float g_bc[ROWS * 2 * NST];
__device__ float g_g [ROWS * FH];     // ffn gate preact (fp32, R for silu-mul)
__device__ float g_p0[ROWS * DM];     // K-split partials
__device__ float g_p1[ROWS * DM];
// fp16 activations (GEMM A operands)
__device__ __half g_h16[ROWS * DM];
__device__ __half g_a16[ROWS * DIN];
__device__ __half g_y16[ROWS * DIN];
__device__ __half g_g16[ROWS * FH];
// fp16 weights
__device__ __half g_win16 [DIN * DM];
__device__ __half g_wgt16 [DIN * DM];
__device__ __half g_wdt16 [DIN * DIN];
__device__ __half g_wx16  [2 * NST * DIN];
__device__ __half g_wout16[DM * DIN];
__device__ __half g_wfg16 [FH * DM];
__device__ __half g_wfu16 [FH * DM];
__device__ __half g_wfd16 [DM * FH];

constexpr int SW   = 20;             // smem row stride in 4-byte words (32 half cols + pad)
constexpr int ASTG = 128 * SW;       // words per stage per matrix
constexpr int STAGES = 4;

__device__ __forceinline__ uint32_t s2u(const void* p) {
    uint32_t a;
    asm("{ .reg .u64 t; cvta.to.shared.u64 t, %1; cvt.u32.u64 %0, t; }" : "=r"(a) : "l"(p));
    return a;
}
__device__ __forceinline__ void cpa16(uint32_t dst, const __half* src, int szbytes) {
    asm volatile("cp.async.cg.shared.global [%0], [%1], 16, %2;"
                 :: "r"(dst), "l"(src), "r"(szbytes));
}
#define CP_COMMIT() asm volatile("cp.async.commit_group;" ::: "memory")
#define CP_WAIT2()  asm volatile("cp.async.wait_group 2;" ::: "memory")

__device__ __forceinline__ void mma_f16(float c[4],
                                        uint32_t a0, uint32_t a1, uint32_t a2, uint32_t a3,
                                        uint32_t b0, uint32_t b1) {
    asm volatile(
        "mma.sync.aligned.m16n8k16.row.col.f32.f16.f16.f32 "
        "{%0,%1,%2,%3}, {%4,%5,%6,%7}, {%8,%9}, {%0,%1,%2,%3};"
        : "+f"(c[0]), "+f"(c[1]), "+f"(c[2]), "+f"(c[3])
        : "r"(a0), "r"(a1), "r"(a2), "r"(a3), "r"(b0), "r"(b1));
}

enum { EP_NONE = 0, EP_GATEMUL, EP_SOFTPLUS, EP_SILUMUL };

__device__ __forceinline__ float sigm(float x) { return 1.0f / (1.0f + expf(-x)); }
__device__ __forceinline__ float sftp(float x) { return (x > 20.0f) ? x : log1pf(expf(x)); }

// ---------------------------------------------------------------------------
// fp16 GEMM: C = epilogue(A[M,K] @ W[N,K]^T), fp32 accumulate.
// BM=BN=128, BK=32, 128 threads (4 warps 2x2), warp tile 64x64 (MT=4, NT=8),
// m16n8k16, 4-stage cp.async, 2 CTAs/SM.
// K-split: P1 != nullptr -> blockIdx.z=1 reads at column offset K, writes P1.
// Folded side-block (last blockIdx.x, W2 != nullptr): C2 = A@W2^T, N2=32.
// ---------------------------------------------------------------------------
template<int EP>
__global__ void __launch_bounds__(128, 2) gemm_h(
    const __half* __restrict__ A, const __half* __restrict__ W,
    const float* __restrict__ R, const float* __restrict__ bias,
    float* __restrict__ C, __half* __restrict__ C16,
    int M, int N, int K, int lda, int ldw,
    const __half* __restrict__ W2, float* __restrict__ C2,
    float* __restrict__ P1)
{
    constexpr int MT = 4, NT = 8;
    extern __shared__ uint32_t sm[];
    uint32_t* As = sm;
    uint32_t* Bs = sm + STAGES * ASTG;
    const uint32_t sbA = s2u(As), sbB = s2u(Bs);

    const int tid  = threadIdx.x;
    const int wid  = tid >> 5, lane = tid & 31;
    const int wm   = wid >> 1, wn = wid & 1;
    const int bm   = blockIdx.y << 7;
    const int bx   = blockIdx.x;
    const int bz   = blockIdx.z;
    const int koff = bz * K;
    float* Cw      = (P1 != nullptr && bz == 1) ? P1 : C;
    const bool isbc = (W2 != nullptr) && (bx == (int)gridDim.x - 1);
    const int bn   = isbc ? 0 : (bx << 7);
    const int Nw   = isbc ? 32 : N;
    const __half* Wk = isbc ? W2 : W;
    const int lr   = lane >> 2, lc = lane & 3;

    float acc[MT][NT][4];
    #pragma unroll
    for (int i = 0; i < MT; i++)
        #pragma unroll
        for (int j = 0; j < NT; j++)
            #pragma unroll
            for (int q = 0; q < 4; q++) acc[i][j][q] = 0.0f;

    const int row0 = tid >> 2;               // +32 per j
    const int kh   = (tid & 3) << 3;         // half-offset within 32-col stage
    const int NS   = K >> 5;                 // BK = 32

    const __half* asrc[4];
    const __half* bsrc[4];
    uint32_t adst[4], bdst[4];
    int bval[4];
    #pragma unroll
    for (int j = 0; j < 4; j++) {
        const int r = row0 + 32 * j;
        asrc[j] = A + (size_t)(bm + r) * lda + koff + kh;
        adst[j] = sbA + (uint32_t)((r * SW + (tid & 3) * 4) << 2);
        bval[j] = (bn + r < Nw) ? 16 : 0;
        bsrc[j] = Wk + (size_t)min(bn + r, Nw - 1) * ldw + koff + kh;
        bdst[j] = sbB + (uint32_t)((r * SW + (tid & 3) * 4) << 2);
    }
    constexpr uint32_t STGB = ASTG * 4;

    auto issue = [&](int st, int k0) {
        #pragma unroll
        for (int j = 0; j < 4; j++) cpa16(adst[j] + st * STGB, asrc[j] + k0, 16);
        #pragma unroll
        for (int j = 0; j < 4; j++) cpa16(bdst[j] + st * STGB, bsrc[j] + k0, bval[j]);
        CP_COMMIT();
    };

    issue(0, 0);
    issue(1, 32);
    issue(2, 64);

    const int fa_base = (wm * 64 + lr) * SW + lc;
    const int fb_base = (wn * 64 + lr) * SW + lc;

    for (int ks = 0; ks < NS; ks++) {
        const int buf = ks & 3;
        CP_WAIT2();
        __syncthreads();

        if (ks + 3 < NS) issue((ks + 3) & 3, (ks + 3) << 5);
        else CP_COMMIT();

        const uint32_t* Asb = As + buf * ASTG;
        const uint32_t* Bsb = Bs + buf * ASTG;

        #pragma unroll
        for (int kc = 0; kc < 2; kc++) {       // two k16 steps per BK=32
            const int kp = kc * 8;             // pair offset within row
            uint32_t af[MT][4], bf[NT][2];
            #pragma unroll
            for (int tm = 0; tm < MT; tm++) {
                const int base = fa_base + tm * 16 * SW + kp;
                af[tm][0] = Asb[base];
                af[tm][1] = Asb[base + 8 * SW];
                af[tm][2] = Asb[base + 4];
                af[tm][3] = Asb[base + 8 * SW + 4];
            }
            #pragma unroll
            for (int tn = 0; tn < NT; tn++) {
                const int base = fb_base + tn * 8 * SW + kp;
                bf[tn][0] = Bsb[base];
                bf[tn][1] = Bsb[base + 4];
            }
            #pragma unroll
            for (int tm = 0; tm < MT; tm++)
                #pragma unroll
                for (int tn = 0; tn < NT; tn++)
                    mma_f16(acc[tm][tn], af[tm][0], af[tm][1], af[tm][2], af[tm][3],
                            bf[tn][0], bf[tn][1]);
        }
    }

    if (isbc) {
        #pragma unroll
        for (int tm = 0; tm < MT; tm++) {
            const int row = bm + wm * 64 + tm * 16 + lr;
            #pragma unroll
            for (int tn = 0; tn < NT; tn++) {
                const int col = wn * 64 + tn * 8 + lc * 2;
                if (col < 32) {
                    *(float2*)(C2 + (size_t)row * 32 + col) =
                        make_float2(acc[tm][tn][0], acc[tm][tn][1]);
                    *(float2*)(C2 + (size_t)(row + 8) * 32 + col) =
                        make_float2(acc[tm][tn][2], acc[tm][tn][3]);
                }
            }
        }
        return;
    }

    #pragma unroll
    for (int tm = 0; tm < MT; tm++) {
        const int row = bm + wm * 64 + tm * 16 + lr;
        #pragma unroll
        for (int tn = 0; tn < NT; tn++) {
            const int col = bn + wn * 64 + tn * 8 + lc * 2;
            if (col < N) {
                #pragma unroll
                for (int hf = 0; hf < 2; hf++) {
                    const size_t o = (size_t)(row + hf * 8) * N + col;
                    float v0 = acc[tm][tn][hf * 2], v1 = acc[tm][tn][hf * 2 + 1];
                    if (EP == EP_NONE) {
                        *(float2*)(Cw + o) = make_float2(v0, v1);
                    } else if (EP == EP_GATEMUL) {
                        const float2 r = *(const float2*)(R + o);
                        v0 = r.x * sigm(v0); v1 = r.y * sigm(v1);
                        *(float2*)(C + o) = make_float2(v0, v1);
                        *(__half2*)(C16 + o) = __floats2half2_rn(v0, v1);
                    } else if (EP == EP_SOFTPLUS) {
                        const float2 bv = *(const float2*)(bias + col);
                        *(float2*)(C + o) = make_float2(sftp(v0 + bv.x), sftp(v1 + bv.y));
                    } else if (EP == EP_SILUMUL) {
                        const float2 r = *(const float2*)(R + o);
                        v0 = r.x * sigm(r.x) * v0; v1 = r.y * sigm(r.y) * v1;
                        *(__half2*)(C16 + o) = __floats2half2_rn(v0, v1);
                    }
                }
            }
        }
    }
}

// ---------------------------------------------------------------------------
// fp32 -> fp16 convert (weights)
// ---------------------------------------------------------------------------
__global__ void __launch_bounds__(256) cvt_kernel(
    const float4* __restrict__ src, __half2* __restrict__ dst, int n4)
{
    const int i = blockIdx.x * 256 + threadIdx.x;
    if (i < n4) {
        const float4 v = src[i];
        dst[2 * i]     = __floats2half2_rn(v.x, v.y);
        dst[2 * i + 1] = __floats2half2_rn(v.z, v.w);
    }
}

// ---------------------------------------------------------------------------
// RMSNorm -> fp16 output
// ---------------------------------------------------------------------------
__global__ void __launch_bounds__(256) rmsnorm16_kernel(
    const float* __restrict__ x, const float* __restrict__ w, __half* __restrict__ out)
{
    __shared__ float red[8];
    const int row = blockIdx.x;
    const int tid = threadIdx.x;
    const float4 v = ((const float4*)(x + (size_t)row * DM))[tid];
    float s = v.x*v.x + v.y*v.y + v.z*v.z + v.w*v.w;
    #pragma unroll
    for (int o = 16; o; o >>= 1) s += __shfl_xor_sync(0xffffffffu, s, o);
    if ((tid & 31) == 0) red[tid >> 5] = s;
    __syncthreads();
    if (tid < 8) {
        float t = red[tid];
        #pragma unroll
        for (int o = 4; o; o >>= 1) t += __shfl_xor_sync(0xffu, t, o);
        if (tid == 0) red[0] = t;
    }
    __syncthreads();
    const float scale = rsqrtf(red[0] * (1.0f / DM) + 1e-6f);
    const float4 wv = ((const float4*)w)[tid];
    __half2* op = (__half2*)(out + (size_t)row * DM) + tid * 2;
    op[0] = __floats2half2_rn(v.x * scale * wv.x, v.y * scale * wv.y);
    op[1] = __floats2half2_rn(v.z * scale * wv.z, v.w * scale * wv.w);
}

// ---------------------------------------------------------------------------
// x2 = x + p0 + p1 ; h16 = fp16(rmsnorm(x2, w))
// ---------------------------------------------------------------------------
__global__ void __launch_bounds__(256) combine_norm_kernel(
    const float* __restrict__ x, const float* __restrict__ w,
    float* __restrict__ x2, __half* __restrict__ h16)
{
    __shared__ float red[8];
    const int row = blockIdx.x;
    const int tid = threadIdx.x;
    const size_t o = (size_t)row * DM / 4 + tid;
    const float4 xv = ((const float4*)x)[o];
    const float4 p0 = ((const float4*)g_p0)[o];
    const float4 p1 = ((const float4*)g_p1)[o];
    float4 v;
    v.x = xv.x + p0.x + p1.x; v.y = xv.y + p0.y + p1.y;
    v.z = xv.z + p0.z + p1.z; v.w = xv.w + p0.w + p1.w;
    ((float4*)x2)[o] = v;
    float s = v.x*v.x + v.y*v.y + v.z*v.z + v.w*v.w;
    #pragma unroll
    for (int of = 16; of; of >>= 1) s += __shfl_xor_sync(0xffffffffu, s, of);
    if ((tid & 31) == 0) red[tid >> 5] = s;
    __syncthreads();
    if (tid < 8) {
        float t = red[tid];
        #pragma unroll
        for (int of = 4; of; of >>= 1) t += __shfl_xor_sync(0xffu, t, of);
        if (tid == 0) red[0] = t;
    }
    __syncthreads();
    const float scale = rsqrtf(red[0] * (1.0f / DM) + 1e-6f);
    const float4 wv = ((const float4*)w)[tid];
    __half2* op = (__half2*)(h16 + (size_t)row * DM) + tid * 2;
    op[0] = __floats2half2_rn(v.x * scale * wv.x, v.y * scale * wv.y);
    op[1] = __floats2half2_rn(v.z * scale * wv.z, v.w * scale * wv.w);
}

// out = x2 + p0 + p1
__global__ void __launch_bounds__(256) combine_add_kernel(
    const float* __restrict__ x2, float* __restrict__ out)
{
    const size_t i = (size_t)blockIdx.x * 256 + threadIdx.x;
    const float4 a = ((const float4*)x2)[i];
    const float4 p0 = ((const float4*)g_p0)[i];
    const float4 p1 = ((const float4*)g_p1)[i];
    float4 v;
    v.x = a.x + p0.x + p1.x; v.y = a.y + p0.y + p1.y;
    v.z = a.z + p0.z + p1.z; v.w = a.w + p0.w + p1.w;
    ((float4*)out)[i] = v;
}

// ---------------------------------------------------------------------------
// Selective scan (16 lanes per channel) -> y16 fp16
// ---------------------------------------------------------------------------
__global__ void __launch_bounds__(256) scan_kernel(
    const float* __restrict__ A_log, const float* __restrict__ Dp)
{
    const int tid = threadIdx.x;
    const int ch  = blockIdx.x * 16 + (tid >> 4);
    const int n   = tid & 15;
    const int b   = ch / DIN;
    const int e   = ch % DIN;

    const float An  = -__expf(A_log[(size_t)e * NST + n]);
    const float dpe = Dp[e];

    const float* dtp = g_b  + (size_t)b * SEQ * DIN + e;
    const float* zp  = g_a  + (size_t)b * SEQ * DIN + e;
    const float* bcp = g_bc + (size_t)b * SEQ * 32;
    __half*      yp  = g_y16 + (size_t)b * SEQ * DIN + e;

    float state = 0.0f;
    #pragma unroll 4
    for (int t = 0; t < SEQ; t++) {
        const float dtv = __ldg(dtp + (size_t)t * DIN);
        const float zv  = __ldg(zp  + (size_t)t * DIN);
        const float Bn  = bcp[t * 32 + n];
        const float Cn  = bcp[t * 32 + 16 + n];
        state = __expf(dtv * An) * state + dtv * zv * Bn;
        float s = state * Cn;
        s += __shfl_xor_sync(0xffffffffu, s, 8);
        s += __shfl_xor_sync(0xffffffffu, s, 4);
        s += __shfl_xor_sync(0xffffffffu, s, 2);
        s += __shfl_xor_sync(0xffffffffu, s, 1);
        if (n == 0) yp[(size_t)t * DIN] = __float2half_rn(s + zv * dpe);
    }
}

// ---------------------------------------------------------------------------
// Launch
// ---------------------------------------------------------------------------
extern "C" void kernel_launch(void* const* d_in, const int* in_sizes, int n_in,
                              void* d_out, int out_size)
{
    const float* x          = (const float*)d_in[0];
    const float* norm1_w    = (const float*)d_in[1];
    const float* in_proj_w  = (const float*)d_in[2];
    const float* gate_proj_w= (const float*)d_in[3];
    const float* dt_w       = (const float*)d_in[4];
    const float* dt_b       = (const float*)d_in[5];
    const float* x_proj_w   = (const float*)d_in[6];
    const float* A_log      = (const float*)d_in[7];
    const float* Dp         = (const float*)d_in[8];
    const float* out_proj_w = (const float*)d_in[9];
    const float* ffn_norm_w = (const float*)d_in[10];
    const float* ffn_gate_w = (const float*)d_in[11];
    const float* ffn_up_w   = (const float*)d_in[12];
    const float* ffn_down_w = (const float*)d_in[13];
    float* out = (float*)d_out;

    float *a, *bb, *x2, *gg, *bc, *p0, *p1;
    __half *h16, *a16, *y16, *g16;
    __half *win, *wgt, *wdt, *wx, *wout, *wfg, *wfu, *wfd;
    cudaGetSymbolAddress((void**)&a,   g_a);
    cudaGetSymbolAddress((void**)&bb,  g_b);
    cudaGetSymbolAddress((void**)&x2,  g_x2);
    cudaGetSymbolAddress((void**)&gg,  g_g);
    cudaGetSymbolAddress((void**)&bc,  g_bc);
    cudaGetSymbolAddress((void**)&p0,  g_p0);
    cudaGetSymbolAddress((void**)&p1,  g_p1);
    cudaGetSymbolAddress((void**)&h16, g_h16);
    cudaGetSymbolAddress((void**)&a16, g_a16);
    cudaGetSymbolAddress((void**)&y16, g_y16);
    cudaGetSymbolAddress((void**)&g16, g_g16);
    cudaGetSymbolAddress((void**)&win, g_win16);
    cudaGetSymbolAddress((void**)&wgt, g_wgt16);
    cudaGetSymbolAddress((void**)&wdt, g_wdt16);
    cudaGetSymbolAddress((void**)&wx,  g_wx16);
    cudaGetSymbolAddress((void**)&wout,g_wout16);
    cudaGetSymbolAddress((void**)&wfg, g_wfg16);
    cudaGetSymbolAddress((void**)&wfu, g_wfu16);
    cudaGetSymbolAddress((void**)&wfd, g_wfd16);

    const int SMEM = STAGES * ASTG * 4 * 2;   // 81920 bytes

    cudaFuncSetAttribute((const void*)gemm_h<EP_NONE>,     cudaFuncAttributeMaxDynamicSharedMemorySize, SMEM);
    cudaFuncSetAttribute((const void*)gemm_h<EP_GATEMUL>,  cudaFuncAttributeMaxDynamicSharedMemorySize, SMEM);
    cudaFuncSetAttribute((const void*)gemm_h<EP_SOFTPLUS>, cudaFuncAttributeMaxDynamicSharedMemorySize, SMEM);
    cudaFuncSetAttribute((const void*)gemm_h<EP_SILUMUL>,  cudaFuncAttributeMaxDynamicSharedMemorySize, SMEM);

    const dim3 blk256(256), blk128(128);

    // 0. Convert weights to fp16
    auto cvt = [&](const float* s, __half* d, int n) {
        cvt_kernel<<<(n / 4 + 255) / 256, blk256>>>((const float4*)s, (__half2*)d, n / 4);
    };
    cvt(in_proj_w,   win,  DIN * DM);
    cvt(gate_proj_w, wgt,  DIN * DM);
    cvt(dt_w,        wdt,  DIN * DIN);
    cvt(x_proj_w,    wx,   2 * NST * DIN);
    cvt(out_proj_w,  wout, DM * DIN);
    cvt(ffn_gate_w,  wfg,  FH * DM);
    cvt(ffn_up_w,    wfu,  FH * DM);
    cvt(ffn_down_w,  wfd,  DM * FH);

    // 1. h16 = fp16(rmsnorm(x))
    rmsnorm16_kernel<<<ROWS, blk256>>>(x, norm1_w, h16);

    // 2. a = h @ in_proj^T (fp32) ; z = a * sigmoid(h @ gate_proj^T) -> fp32 a + fp16 a16
    gemm_h<EP_NONE>   <<<dim3(DIN/128, ROWS/128), blk128, SMEM>>>(h16, win, nullptr, nullptr, a,  nullptr, ROWS, DIN, DM, DM, DM, nullptr, nullptr, nullptr);
    gemm_h<EP_GATEMUL><<<dim3(DIN/128, ROWS/128), blk128, SMEM>>>(h16, wgt, a,       nullptr, a,  a16,     ROWS, DIN, DM, DM, DM, nullptr, nullptr, nullptr);

    // 3. dt = softplus(z @ dt_w^T + dt_b)  [+ folded BC = z @ x_proj^T]
    gemm_h<EP_SOFTPLUS><<<dim3(DIN/128 + 1, ROWS/128), blk128, SMEM>>>(a16, wdt, nullptr, dt_b, bb, nullptr, ROWS, DIN, DIN, DIN, DIN, wx, bc, nullptr);

    // 4. scan -> y16
    scan_kernel<<<(BATCH * DIN) / 16, blk256>>>(A_log, Dp);

    // 5. p0/p1 = y @ out_proj^T (K-split); x2 = x + p0 + p1 ; h16 = fp16(rmsnorm(x2))
    gemm_h<EP_NONE><<<dim3(DM/128, ROWS/128, 2), blk128, SMEM>>>(y16, wout, nullptr, nullptr, p0, nullptr, ROWS, DM, DIN/2, DIN, DIN, nullptr, nullptr, p1);
    combine_norm_kernel<<<ROWS, blk256>>>(x, ffn_norm_w, x2, h16);

    // 6. FFN: gg = hn @ Wg^T (fp32) ; g16 = fp16(silu(gg) * (hn @ Wu^T))
    gemm_h<EP_NONE>   <<<dim3((FH+127)/128, ROWS/128), blk128, SMEM>>>(h16, wfg, nullptr, nullptr, gg, nullptr, ROWS, FH, DM, DM, DM, nullptr, nullptr, nullptr);
    gemm_h<EP_SILUMUL><<<dim3((FH+127)/128, ROWS/128), blk128, SMEM>>>(h16, wfu, gg,      nullptr, nullptr, g16, ROWS, FH, DM, DM, DM, nullptr, nullptr, nullptr);

    // 7. p0/p1 = g16 @ Wd^T (K-split); out = x2 + p0 + p1
    gemm_h<EP_NONE><<<dim3(DM/128, ROWS/128, 2), blk128, SMEM>>>(g16, wfd, nullptr, nullptr, p0, nullptr, ROWS, DM, FH/2, FH, FH, nullptr, nullptr, p1);
    combine_add_kernel<<<(ROWS * DM) / 1024, blk256>>>(x2, out);
}

// round 11
// speedup vs baseline: 1.6133x; 1.0662x over previous
#include <cuda_runtime.h>
#include <cuda_fp16.h>
#include <math.h>
#include <stdint.h>

// Problem dims
constexpr int BATCH = 2;
constexpr int SEQ   = 1024;
constexpr int DM    = 1024;
constexpr int DIN   = 2048;
constexpr int NST   = 16;
constexpr int FH    = 2752;
constexpr int ROWS  = BATCH * SEQ;  // 2048

// fp32 scratch
__device__ float g_a [ROWS * DIN];    // z (fp32, for scan)
__device__ float g_b [ROWS * DIN];    // dt
__device__ float g_x2[ROWS * DM];
__device__ float g_bc[ROWS * 2 * NST];
__device__ float g_g [ROWS * FH];     // ffn gate preact
__device__ float g_p0[ROWS * DM];     // K-split partials
__device__ float g_p1[ROWS * DM];
// fp16 activations
__device__ __half g_h16[ROWS * DM];
__device__ __half g_a16[ROWS * DIN];
__device__ __half g_y16[ROWS * DIN];
__device__ __half g_g16[ROWS * FH];
// fp16 weights
__device__ __half g_win16 [DIN * DM];
__device__ __half g_wgt16 [DIN * DM];
__device__ __half g_wdt16 [DIN * DIN];
__device__ __half g_wx16  [2 * NST * DIN];
__device__ __half g_wout16[DM * DIN];
__device__ __half g_wfg16 [FH * DM];
__device__ __half g_wfu16 [FH * DM];
__device__ __half g_wfd16 [DM * FH];

constexpr int SW   = 36;             // smem row stride in 4-byte words (64 halfs + 4 pad)
constexpr int ASTG = 128 * SW;       // words per stage per matrix
constexpr int STAGES = 3;

__device__ __forceinline__ uint32_t s2u(const void* p) {
    uint32_t a;
    asm("{ .reg .u64 t; cvta.to.shared.u64 t, %1; cvt.u32.u64 %0, t; }" : "=r"(a) : "l"(p));
    return a;
}
__device__ __forceinline__ void cpa16(uint32_t dst, const __half* src, int szbytes) {
    asm volatile("cp.async.cg.shared.global [%0], [%1], 16, %2;"
                 :: "r"(dst), "l"(src), "r"(szbytes));
}
#define CP_COMMIT() asm volatile("cp.async.commit_group;" ::: "memory")
#define CP_WAIT1()  asm volatile("cp.async.wait_group 1;" ::: "memory")

__device__ __forceinline__ void mma_f16(float c[4],
                                        uint32_t a0, uint32_t a1, uint32_t a2, uint32_t a3,
                                        uint32_t b0, uint32_t b1) {
    asm volatile(
        "mma.sync.aligned.m16n8k16.row.col.f32.f16.f16.f32 "
        "{%0,%1,%2,%3}, {%4,%5,%6,%7}, {%8,%9}, {%0,%1,%2,%3};"
        : "+f"(c[0]), "+f"(c[1]), "+f"(c[2]), "+f"(c[3])
        : "r"(a0), "r"(a1), "r"(a2), "r"(a3), "r"(b0), "r"(b1));
}

enum { EP_NONE = 0, EP_GATEMUL, EP_SOFTPLUS, EP_SILUMUL };

__device__ __forceinline__ float sigm(float x) { return 1.0f / (1.0f + expf(-x)); }
__device__ __forceinline__ float sftp(float x) { return (x > 20.0f) ? x : log1pf(expf(x)); }

// ---------------------------------------------------------------------------
// fp16 GEMM: C = epilogue(A[M,K] @ W[N,K]^T), fp32 accumulate.
// BM=BN=128, BK=64, 128 threads (4 warps 2x2), warp tile 64x64, m16n8k16,
// 3-stage cp.async (110.6KB smem/CTA, 2 CTA/SM).
// K-split: P1 != nullptr -> blockIdx.z=1 reads at column offset Kz0, extent K2,
// writes P1.  Folded side-block (last bx, W2 != nullptr): C2 = A@W2^T, N2=32.
// ---------------------------------------------------------------------------
template<int EP>
__global__ void __launch_bounds__(128, 2) gemm_h(
    const __half* __restrict__ A, const __half* __restrict__ W,
    const float* __restrict__ R, const float* __restrict__ bias,
    float* __restrict__ C, __half* __restrict__ C16,
    int M, int N, int K, int K2, int lda, int ldw,
    const __half* __restrict__ W2, float* __restrict__ C2,
    float* __restrict__ P1)
{
    constexpr int MT = 4, NT = 8;
    extern __shared__ uint32_t sm[];
    uint32_t* As = sm;
    uint32_t* Bs = sm + STAGES * ASTG;
    const uint32_t sbA = s2u(As), sbB = s2u(Bs);

    const int tid  = threadIdx.x;
    const int wid  = tid >> 5, lane = tid & 31;
    const int wm   = wid >> 1, wn = wid & 1;
    const int bm   = blockIdx.y << 7;
    const int bx   = blockIdx.x;
    const int bz   = blockIdx.z;
    const int koff = bz * K;                  // z=1 starts where z=0's extent ends
    const int Kext = bz ? K2 : K;
    float* Cw      = (P1 != nullptr && bz == 1) ? P1 : C;
    const bool isbc = (W2 != nullptr) && (bx == (int)gridDim.x - 1);
    const int bn   = isbc ? 0 : (bx << 7);
    const int Nw   = isbc ? 32 : N;
    const __half* Wk = isbc ? W2 : W;
    const int lr   = lane >> 2, lc = lane & 3;

    float acc[MT][NT][4];
    #pragma unroll
    for (int i = 0; i < MT; i++)
        #pragma unroll
        for (int j = 0; j < NT; j++)
            #pragma unroll
            for (int q = 0; q < 4; q++) acc[i][j][q] = 0.0f;

    // Load mapping: thread covers 8 (row, 16B-chunk) pairs per matrix per stage.
    const int row0 = tid >> 3;                // 0..15, +16 per j
    const int ch   = tid & 7;                 // 16B chunk within 128B row
    const int kh   = ch << 3;                 // half offset
    const int NS   = Kext >> 6;               // BK = 64

    const __half* abase = A  + (size_t)(bm + row0) * lda + koff + kh;
    const int     brow  = bn + row0;
    const uint32_t adst0 = sbA + (uint32_t)((row0 * SW + ch * 4) << 2);
    const uint32_t bdst0 = sbB + (uint32_t)((row0 * SW + ch * 4) << 2);
    constexpr uint32_t STGB = ASTG * 4;
    constexpr uint32_t ROWB = 16 * SW * 4;    // 16 rows stride in bytes
    const size_t lda16 = (size_t)lda * 16;
    const size_t ldw16 = (size_t)ldw * 16;

    const __half* bbase[8];
    int bval[8];
    #pragma unroll
    for (int j = 0; j < 8; j++) {
        const int r = brow + 16 * j;
        bval[j]  = (r < Nw) ? 16 : 0;
        bbase[j] = Wk + (size_t)min(r, Nw - 1) * ldw + koff + kh;
    }

    auto issue = [&](int st, int k0) {
        const uint32_t da = adst0 + st * STGB;
        const uint32_t db = bdst0 + st * STGB;
        #pragma unroll
        for (int j = 0; j < 8; j++) cpa16(da + j * ROWB, abase + j * lda16 + k0, 16);
        #pragma unroll
        for (int j = 0; j < 8; j++) cpa16(db + j * ROWB, bbase[j] + k0, bval[j]);
        CP_COMMIT();
    };

    issue(0, 0);
    issue(1, 64);

    const int fa_base = (wm * 64 + lr) * SW + lc;
    const int fb_base = (wn * 64 + lr) * SW + lc;

    int buf = 0;
    for (int ks = 0; ks < NS; ks++) {
        CP_WAIT1();
        __syncthreads();

        if (ks + 2 < NS) {
            int nb = buf + 2; if (nb >= 3) nb -= 3;
            issue(nb, (ks + 2) << 6);
        } else CP_COMMIT();

        const uint32_t* Asb = As + buf * ASTG;
        const uint32_t* Bsb = Bs + buf * ASTG;

        #pragma unroll
        for (int kc = 0; kc < 4; kc++) {       // four k16 steps per BK=64
            const int kp = kc * 8;
            uint32_t af[MT][4], bf[NT][2];
            #pragma unroll
            for (int tm = 0; tm < MT; tm++) {
                const int base = fa_base + tm * 16 * SW + kp;
                af[tm][0] = Asb[base];
                af[tm][1] = Asb[base + 8 * SW];
                af[tm][2] = Asb[base + 4];
                af[tm][3] = Asb[base + 8 * SW + 4];
            }
            #pragma unroll
            for (int tn = 0; tn < NT; tn++) {
                const int base = fb_base + tn * 8 * SW + kp;
                bf[tn][0] = Bsb[base];
                bf[tn][1] = Bsb[base + 4];
            }
            #pragma unroll
            for (int tm = 0; tm < MT; tm++)
                #pragma unroll
                for (int tn = 0; tn < NT; tn++)
                    mma_f16(acc[tm][tn], af[tm][0], af[tm][1], af[tm][2], af[tm][3],
                            bf[tn][0], bf[tn][1]);
        }
        if (++buf == 3) buf = 0;
    }

    if (isbc) {
        #pragma unroll
        for (int tm = 0; tm < MT; tm++) {
            const int row = bm + wm * 64 + tm * 16 + lr;
            #pragma unroll
            for (int tn = 0; tn < NT; tn++) {
                const int col = wn * 64 + tn * 8 + lc * 2;
                if (col < 32) {
                    *(float2*)(C2 + (size_t)row * 32 + col) =
                        make_float2(acc[tm][tn][0], acc[tm][tn][1]);
                    *(float2*)(C2 + (size_t)(row + 8) * 32 + col) =
                        make_float2(acc[tm][tn][2], acc[tm][tn][3]);
                }
            }
        }
        return;
    }

    #pragma unroll
    for (int tm = 0; tm < MT; tm++) {
        const int row = bm + wm * 64 + tm * 16 + lr;
        #pragma unroll
        for (int tn = 0; tn < NT; tn++) {
            const int col = bn + wn * 64 + tn * 8 + lc * 2;
            if (col < N) {
                #pragma unroll
                for (int hf = 0; hf < 2; hf++) {
                    const size_t o = (size_t)(row + hf * 8) * N + col;
                    float v0 = acc[tm][tn][hf * 2], v1 = acc[tm][tn][hf * 2 + 1];
                    if (EP == EP_NONE) {
                        *(float2*)(Cw + o) = make_float2(v0, v1);
                    } else if (EP == EP_GATEMUL) {
                        const float2 r = *(const float2*)(R + o);
                        v0 = r.x * sigm(v0); v1 = r.y * sigm(v1);
                        *(float2*)(C + o) = make_float2(v0, v1);
                        *(__half2*)(C16 + o) = __floats2half2_rn(v0, v1);
                    } else if (EP == EP_SOFTPLUS) {
                        const float2 bv = *(const float2*)(bias + col);
                        *(float2*)(C + o) = make_float2(sftp(v0 + bv.x), sftp(v1 + bv.y));
                    } else if (EP == EP_SILUMUL) {
                        const float2 r = *(const float2*)(R + o);
                        v0 = r.x * sigm(r.x) * v0; v1 = r.y * sigm(r.y) * v1;
                        *(__half2*)(C16 + o) = __floats2half2_rn(v0, v1);
                    }
                }
            }
        }
    }
}

// ---------------------------------------------------------------------------
// Fused fp32->fp16 conversion of all 8 weight matrices in one launch.
// ---------------------------------------------------------------------------
struct CvtJobs {
    const float4* src[8];
    __half2* dst[8];
    int cum[9];    // prefix sums of float4 counts
};

__global__ void __launch_bounds__(256) cvt_all_kernel(CvtJobs jobs)
{
    int i = blockIdx.x * 256 + threadIdx.x;
    if (i >= jobs.cum[8]) return;
    int j = 0;
    #pragma unroll
    for (int t = 1; t < 8; t++) j += (i >= jobs.cum[t]);
    const int li = i - jobs.cum[j];
    const float4 v = jobs.src[j][li];
    jobs.dst[j][2 * li]     = __floats2half2_rn(v.x, v.y);
    jobs.dst[j][2 * li + 1] = __floats2half2_rn(v.z, v.w);
}

// ---------------------------------------------------------------------------
// RMSNorm -> fp16 output
// ---------------------------------------------------------------------------
__global__ void __launch_bounds__(256) rmsnorm16_kernel(
    const float* __restrict__ x, const float* __restrict__ w, __half* __restrict__ out)
{
    __shared__ float red[8];
    const int row = blockIdx.x;
    const int tid = threadIdx.x;
    const float4 v = ((const float4*)(x + (size_t)row * DM))[tid];
    float s = v.x*v.x + v.y*v.y + v.z*v.z + v.w*v.w;
    #pragma unroll
    for (int o = 16; o; o >>= 1) s += __shfl_xor_sync(0xffffffffu, s, o);
    if ((tid & 31) == 0) red[tid >> 5] = s;
    __syncthreads();
    if (tid < 8) {
        float t = red[tid];
        #pragma unroll
        for (int o = 4; o; o >>= 1) t += __shfl_xor_sync(0xffu, t, o);
        if (tid == 0) red[0] = t;
    }
    __syncthreads();
    const float scale = rsqrtf(red[0] * (1.0f / DM) + 1e-6f);
    const float4 wv = ((const float4*)w)[tid];
    __half2* op = (__half2*)(out + (size_t)row * DM) + tid * 2;
    op[0] = __floats2half2_rn(v.x * scale * wv.x, v.y * scale * wv.y);
    op[1] = __floats2half2_rn(v.z * scale * wv.z, v.w * scale * wv.w);
}

// ---------------------------------------------------------------------------
// x2 = x + p0 + p1 ; h16 = fp16(rmsnorm(x2, w))
// ---------------------------------------------------------------------------
__global__ void __launch_bounds__(256) combine_norm_kernel(
    const float* __restrict__ x, const float* __restrict__ w,
    float* __restrict__ x2, __half* __restrict__ h16)
{
    __shared__ float red[8];
    const int row = blockIdx.x;
    const int tid = threadIdx.x;
    const size_t o = (size_t)row * DM / 4 + tid;
    const float4 xv = ((const float4*)x)[o];
    const float4 p0 = ((const float4*)g_p0)[o];
    const float4 p1 = ((const float4*)g_p1)[o];
    float4 v;
    v.x = xv.x + p0.x + p1.x; v.y = xv.y + p0.y + p1.y;
    v.z = xv.z + p0.z + p1.z; v.w = xv.w + p0.w + p1.w;
    ((float4*)x2)[o] = v;
    float s = v.x*v.x + v.y*v.y + v.z*v.z + v.w*v.w;
    #pragma unroll
    for (int of = 16; of; of >>= 1) s += __shfl_xor_sync(0xffffffffu, s, of);
    if ((tid & 31) == 0) red[tid >> 5] = s;
    __syncthreads();
    if (tid < 8) {
        float t = red[tid];
        #pragma unroll
        for (int of = 4; of; of >>= 1) t += __shfl_xor_sync(0xffu, t, of);
        if (tid == 0) red[0] = t;
    }
    __syncthreads();
    const float scale = rsqrtf(red[0] * (1.0f / DM) + 1e-6f);
    const float4 wv = ((const float4*)w)[tid];
    __half2* op = (__half2*)(h16 + (size_t)row * DM) + tid * 2;
    op[0] = __floats2half2_rn(v.x * scale * wv.x, v.y * scale * wv.y);
    op[1] = __floats2half2_rn(v.z * scale * wv.z, v.w * scale * wv.w);
}

// out = x2 + p0 + p1
__global__ void __launch_bounds__(256) combine_add_kernel(
    const float* __restrict__ x2, float* __restrict__ out)
{
    const size_t i = (size_t)blockIdx.x * 256 + threadIdx.x;
    const float4 a = ((const float4*)x2)[i];
    const float4 p0 = ((const float4*)g_p0)[i];
    const float4 p1 = ((const float4*)g_p1)[i];
    float4 v;
    v.x = a.x + p0.x + p1.x; v.y = a.y + p0.y + p1.y;
    v.z = a.z + p0.z + p1.z; v.w = a.w + p0.w + p1.w;
    ((float4*)out)[i] = v;
}

// ---------------------------------------------------------------------------
// Selective scan (16 lanes per channel) -> y16 fp16
// ---------------------------------------------------------------------------
__global__ void __launch_bounds__(256) scan_kernel(
    const float* __restrict__ A_log, const float* __restrict__ Dp)
{
    const int tid = threadIdx.x;
    const int ch  = blockIdx.x * 16 + (tid >> 4);
    const int n   = tid & 15;
    const int b   = ch / DIN;
    const int e   = ch % DIN;

    const float An  = -__expf(A_log[(size_t)e * NST + n]);
    const float dpe = Dp[e];

    const float* dtp = g_b  + (size_t)b * SEQ * DIN + e;
    const float* zp  = g_a  + (size_t)b * SEQ * DIN + e;
    const float* bcp = g_bc + (size_t)b * SEQ * 32;
    __half*      yp  = g_y16 + (size_t)b * SEQ * DIN + e;

    float state = 0.0f;
    #pragma unroll 4
    for (int t = 0; t < SEQ; t++) {
        const float dtv = __ldg(dtp + (size_t)t * DIN);
        const float zv  = __ldg(zp  + (size_t)t * DIN);
        const float Bn  = bcp[t * 32 + n];
        const float Cn  = bcp[t * 32 + 16 + n];
        state = __expf(dtv * An) * state + dtv * zv * Bn;
        float s = state * Cn;
        s += __shfl_xor_sync(0xffffffffu, s, 8);
        s += __shfl_xor_sync(0xffffffffu, s, 4);
        s += __shfl_xor_sync(0xffffffffu, s, 2);
        s += __shfl_xor_sync(0xffffffffu, s, 1);
        if (n == 0) yp[(size_t)t * DIN] = __float2half_rn(s + zv * dpe);
    }
}

// ---------------------------------------------------------------------------
// Launch
// ---------------------------------------------------------------------------
extern "C" void kernel_launch(void* const* d_in, const int* in_sizes, int n_in,
                              void* d_out, int out_size)
{
    const float* x          = (const float*)d_in[0];
    const float* norm1_w    = (const float*)d_in[1];
    const float* in_proj_w  = (const float*)d_in[2];
    const float* gate_proj_w= (const float*)d_in[3];
    const float* dt_w       = (const float*)d_in[4];
    const float* dt_b       = (const float*)d_in[5];
    const float* x_proj_w   = (const float*)d_in[6];
    const float* A_log      = (const float*)d_in[7];
    const float* Dp         = (const float*)d_in[8];
    const float* out_proj_w = (const float*)d_in[9];
    const float* ffn_norm_w = (const float*)d_in[10];
    const float* ffn_gate_w = (const float*)d_in[11];
    const float* ffn_up_w   = (const float*)d_in[12];
    const float* ffn_down_w = (const float*)d_in[13];
    float* out = (float*)d_out;

    float *a, *bb, *x2, *gg, *bc, *p0, *p1;
    __half *h16, *a16, *y16, *g16;
    __half *win, *wgt, *wdt, *wx, *wout, *wfg, *wfu, *wfd;
    cudaGetSymbolAddress((void**)&a,   g_a);
    cudaGetSymbolAddress((void**)&bb,  g_b);
    cudaGetSymbolAddress((void**)&x2,  g_x2);
    cudaGetSymbolAddress((void**)&gg,  g_g);
    cudaGetSymbolAddress((void**)&bc,  g_bc);
    cudaGetSymbolAddress((void**)&p0,  g_p0);
    cudaGetSymbolAddress((void**)&p1,  g_p1);
    cudaGetSymbolAddress((void**)&h16, g_h16);
    cudaGetSymbolAddress((void**)&a16, g_a16);
    cudaGetSymbolAddress((void**)&y16, g_y16);
    cudaGetSymbolAddress((void**)&g16, g_g16);
    cudaGetSymbolAddress((void**)&win, g_win16);
    cudaGetSymbolAddress((void**)&wgt, g_wgt16);
    cudaGetSymbolAddress((void**)&wdt, g_wdt16);
    cudaGetSymbolAddress((void**)&wx,  g_wx16);
    cudaGetSymbolAddress((void**)&wout,g_wout16);
    cudaGetSymbolAddress((void**)&wfg, g_wfg16);
    cudaGetSymbolAddress((void**)&wfu, g_wfu16);
    cudaGetSymbolAddress((void**)&wfd, g_wfd16);

    const int SMEM = STAGES * ASTG * 4 * 2;   // 110592 bytes

    cudaFuncSetAttribute((const void*)gemm_h<EP_NONE>,     cudaFuncAttributeMaxDynamicSharedMemorySize, SMEM);
    cudaFuncSetAttribute((const void*)gemm_h<EP_GATEMUL>,  cudaFuncAttributeMaxDynamicSharedMemorySize, SMEM);
    cudaFuncSetAttribute((const void*)gemm_h<EP_SOFTPLUS>, cudaFuncAttributeMaxDynamicSharedMemorySize, SMEM);
    cudaFuncSetAttribute((const void*)gemm_h<EP_SILUMUL>,  cudaFuncAttributeMaxDynamicSharedMemorySize, SMEM);

    const dim3 blk256(256), blk128(128);

    // 0. Convert all weights to fp16 in one launch
    {
        CvtJobs jobs;
        const float* srcs[8] = {in_proj_w, gate_proj_w, dt_w, x_proj_w,
                                out_proj_w, ffn_gate_w, ffn_up_w, ffn_down_w};
        __half* dsts[8] = {win, wgt, wdt, wx, wout, wfg, wfu, wfd};
        const int ns[8] = {DIN*DM, DIN*DM, DIN*DIN, 2*NST*DIN,
                           DM*DIN, FH*DM, FH*DM, DM*FH};
        int cum = 0;
        for (int j = 0; j < 8; j++) {
            jobs.src[j] = (const float4*)srcs[j];
            jobs.dst[j] = (__half2*)dsts[j];
            jobs.cum[j] = cum;
            cum += ns[j] / 4;
        }
        jobs.cum[8] = cum;
        cvt_all_kernel<<<(cum + 255) / 256, blk256>>>(jobs);
    }

    // 1. h16 = fp16(rmsnorm(x))
    rmsnorm16_kernel<<<ROWS, blk256>>>(x, norm1_w, h16);

    // 2. a = h @ in_proj^T ; z = a * sigmoid(h @ gate_proj^T) -> a (fp32) + a16
    gemm_h<EP_NONE>   <<<dim3(DIN/128, ROWS/128), blk128, SMEM>>>(h16, win, nullptr, nullptr, a,  nullptr, ROWS, DIN, DM, 0, DM, DM, nullptr, nullptr, nullptr);
    gemm_h<EP_GATEMUL><<<dim3(DIN/128, ROWS/128), blk128, SMEM>>>(h16, wgt, a,       nullptr, a,  a16,     ROWS, DIN, DM, 0, DM, DM, nullptr, nullptr, nullptr);

    // 3. dt = softplus(z @ dt_w^T + dt_b)  [+ folded BC = z @ x_proj^T]
    gemm_h<EP_SOFTPLUS><<<dim3(DIN/128 + 1, ROWS/128), blk128, SMEM>>>(a16, wdt, nullptr, dt_b, bb, nullptr, ROWS, DIN, DIN, 0, DIN, DIN, wx, bc, nullptr);

    // 4. scan -> y16
    scan_kernel<<<(BATCH * DIN) / 16, blk256>>>(A_log, Dp);

    // 5. p0/p1 = y @ out_proj^T (K-split); x2 = x + p0 + p1 ; h16 = fp16(rmsnorm(x2))
    gemm_h<EP_NONE><<<dim3(DM/128, ROWS/128, 2), blk128, SMEM>>>(y16, wout, nullptr, nullptr, p0, nullptr, ROWS, DM, DIN/2, DIN/2, DIN, DIN, nullptr, nullptr, p1);
    combine_norm_kernel<<<ROWS, blk256>>>(x, ffn_norm_w, x2, h16);

    // 6. FFN: gg = hn @ Wg^T ; g16 = fp16(silu(gg) * (hn @ Wu^T))
    gemm_h<EP_NONE>   <<<dim3((FH+127)/128, ROWS/128), blk128, SMEM>>>(h16, wfg, nullptr, nullptr, gg, nullptr, ROWS, FH, DM, 0, DM, DM, nullptr, nullptr, nullptr);
    gemm_h<EP_SILUMUL><<<dim3((FH+127)/128, ROWS/128), blk128, SMEM>>>(h16, wfu, gg,      nullptr, nullptr, g16, ROWS, FH, DM, 0, DM, DM, nullptr, nullptr, nullptr);

    // 7. p0/p1 = g16 @ Wd^T (uneven K-split 1408/1344); out = x2 + p0 + p1
    gemm_h<EP_NONE><<<dim3(DM/128, ROWS/128, 2), blk128, SMEM>>>(g16, wfd, nullptr, nullptr, p0, nullptr, ROWS, DM, 1408, 1344, FH, FH, nullptr, nullptr, p1);
    combine_add_kernel<<<(ROWS * DM) / 1024, blk256>>>(x2, out);
}